// round 6
// baseline (speedup 1.0000x reference)
#include <cuda_runtime.h>
#include <math.h>

// ---------------- problem constants ----------------
#define Bc   2
#define Tc   2048
#define Ec   1024
#define Hc   16
#define HDc  64
#define Lc   4
#define Vc   32000
#define FFc  4096
#define Mc   (Bc*Tc)      // 4096
#define EPSc 1e-5f

// ---------------- device scratch (static; allocation-free) ----------------
__device__ float g_x[Mc*Ec];                 // residual stream
__device__ float g_h[Mc*Ec];                 // layernorm output
__device__ float g_wt[Ec*3*Ec];              // rearranged QKV weight [E, 3E]
__device__ float g_qkv[Mc*3*Ec];             // [B,T,{q,k,v},H,HD]
__device__ float g_att[Mc*Ec];               // attention out, head-concat layout
__device__ float g_f[(size_t)Mc*FFc];        // MLP hidden
__device__ float g_logits[(size_t)Mc*Vc];    // fallback logits if d_out too small
__device__ float g_rowloss[Mc];

// ---------------- embedding ----------------
__global__ void embed_kernel(const int* __restrict__ idx,
                             const float* __restrict__ tok,
                             const float* __restrict__ pos) {
    int row = blockIdx.x;          // b*T + t
    int t = row & (Tc - 1);
    int token = idx[row];
    const float4* t4 = (const float4*)(tok + (size_t)token * Ec);
    const float4* p4 = (const float4*)(pos + (size_t)t * Ec);
    float4* o4 = (float4*)(g_x + (size_t)row * Ec);
    int i = threadIdx.x;           // 256 threads, E/4 = 256 float4
    float4 a = t4[i], p = p4[i];
    o4[i] = make_float4(a.x + p.x, a.y + p.y, a.z + p.z, a.w + p.w);
}

// ---------------- layernorm (one block per row, 256 thr, E=1024) ----------------
__global__ void ln_kernel(const float* __restrict__ in, float* __restrict__ out,
                          const float* __restrict__ gamma, const float* __restrict__ beta) {
    int row = blockIdx.x;
    int tid = threadIdx.x;
    const float4* in4 = (const float4*)(in + (size_t)row * Ec);
    float4 v = in4[tid];
    float s  = v.x + v.y + v.z + v.w;
    float ss = v.x*v.x + v.y*v.y + v.z*v.z + v.w*v.w;

    __shared__ float rs[8], rss[8];
    #pragma unroll
    for (int o = 16; o; o >>= 1) {
        s  += __shfl_xor_sync(0xffffffffu, s,  o);
        ss += __shfl_xor_sync(0xffffffffu, ss, o);
    }
    if ((tid & 31) == 0) { rs[tid >> 5] = s; rss[tid >> 5] = ss; }
    __syncthreads();
    __shared__ float smean, srstd;
    if (tid == 0) {
        float ts = 0.f, tss = 0.f;
        #pragma unroll
        for (int w = 0; w < 8; w++) { ts += rs[w]; tss += rss[w]; }
        float mean = ts * (1.0f / Ec);
        float var  = tss * (1.0f / Ec) - mean * mean;
        smean = mean;
        srstd = rsqrtf(var + EPSc);
    }
    __syncthreads();
    float mean = smean, rstd = srstd;
    float4 g = ((const float4*)gamma)[tid];
    float4 b = ((const float4*)beta)[tid];
    float4 o;
    o.x = (v.x - mean) * rstd * g.x + b.x;
    o.y = (v.y - mean) * rstd * g.y + b.y;
    o.z = (v.z - mean) * rstd * g.z + b.z;
    o.w = (v.w - mean) * rstd * g.w + b.w;
    ((float4*)(out + (size_t)row * Ec))[tid] = o;
}

// ---------------- QKV weight rearrange: Wt[e, 3E] with col = which*E + h*64 + d ----
__global__ void rearrange_kernel(const float* __restrict__ Wq,
                                 const float* __restrict__ Wk,
                                 const float* __restrict__ Wv, int l) {
    int i = blockIdx.x * 256 + threadIdx.x;  // 0 .. 3*E*E-1
    int e = i / (3 * Ec);
    int n = i - e * (3 * Ec);
    int which = n >> 10;
    int c = n & 1023;
    const float* W = (which == 0) ? Wq : (which == 1 ? Wk : Wv);
    g_wt[i] = W[(((size_t)l * Hc + (c >> 6)) * Ec + e) * HDc + (c & 63)];
}

// ---------------- generic SGEMM: C[M,N] (+=) A[M,K] * B[K,N] (+bias)(relu) -------
// 128x128 block tile, BK=16, 256 threads, 8x8 per thread. All dims multiples of 128/16.
template <bool BIAS, bool RELU, bool RESID>
__global__ __launch_bounds__(256, 2)
void sgemm(const float* __restrict__ A, const float* __restrict__ Bm,
           const float* __restrict__ bias, float* __restrict__ C,
           int Mdim, int Ndim, int Kdim) {
    __shared__ float As[16][132];   // padded: 2-way max conflict on transpose store
    __shared__ float Bs[16][128];

    const int tid = threadIdx.x;
    const int tx = tid & 15, ty = tid >> 4;
    const int brow0 = blockIdx.y * 128;
    const int bcol0 = blockIdx.x * 128;

    float acc[8][8];
    #pragma unroll
    for (int i = 0; i < 8; i++)
        #pragma unroll
        for (int j = 0; j < 8; j++) acc[i][j] = 0.f;

    for (int k0 = 0; k0 < Kdim; k0 += 16) {
        #pragma unroll
        for (int p = 0; p < 2; p++) {
            int fid = p * 256 + tid;
            int ar = fid >> 2, ac = (fid & 3) << 2;
            float4 av = *(const float4*)&A[(size_t)(brow0 + ar) * Kdim + k0 + ac];
            As[ac + 0][ar] = av.x; As[ac + 1][ar] = av.y;
            As[ac + 2][ar] = av.z; As[ac + 3][ar] = av.w;
            int bk = fid >> 5, bc = (fid & 31) << 2;
            *(float4*)&Bs[bk][bc] = *(const float4*)&Bm[(size_t)(k0 + bk) * Ndim + bcol0 + bc];
        }
        __syncthreads();
        #pragma unroll
        for (int kk = 0; kk < 16; kk++) {
            float ra[8], rb[8];
            *(float4*)&ra[0] = *(float4*)&As[kk][ty * 8];
            *(float4*)&ra[4] = *(float4*)&As[kk][ty * 8 + 4];
            *(float4*)&rb[0] = *(float4*)&Bs[kk][tx * 8];
            *(float4*)&rb[4] = *(float4*)&Bs[kk][tx * 8 + 4];
            #pragma unroll
            for (int i = 0; i < 8; i++)
                #pragma unroll
                for (int j = 0; j < 8; j++) acc[i][j] += ra[i] * rb[j];
        }
        __syncthreads();
    }

    #pragma unroll
    for (int i = 0; i < 8; i++) {
        size_t row = (size_t)(brow0 + ty * 8 + i);
        float* crow = C + row * (size_t)Ndim;
        #pragma unroll
        for (int j = 0; j < 8; j += 4) {
            int col = bcol0 + tx * 8 + j;
            float4 v = make_float4(acc[i][j], acc[i][j+1], acc[i][j+2], acc[i][j+3]);
            if (BIAS) {
                float4 bb = *(const float4*)&bias[col];
                v.x += bb.x; v.y += bb.y; v.z += bb.z; v.w += bb.w;
            }
            if (RELU) {
                v.x = fmaxf(v.x, 0.f); v.y = fmaxf(v.y, 0.f);
                v.z = fmaxf(v.z, 0.f); v.w = fmaxf(v.w, 0.f);
            }
            if (RESID) {
                float4 o = *(const float4*)&crow[col];
                v.x += o.x; v.y += o.y; v.z += o.z; v.w += o.w;
            }
            *(float4*)&crow[col] = v;
        }
    }
}

// ---------------- causal flash attention ----------------
// grid (T/64, H, B), 256 threads; 4 threads per query (each owns 16 of 64 dims).
__global__ __launch_bounds__(256, 2)
void attn_kernel() {
    const int qt = blockIdx.x, h = blockIdx.y, b = blockIdx.z;
    const int tid = threadIdx.x;
    const int qid = tid >> 2;       // 0..63
    const int sub = tid & 3;        // 0..3
    const int t = qt * 64 + qid;

    __shared__ float sK[64][64];
    __shared__ float sV[64][64];

    // load + pre-scale q (scale = HD^-0.5 = 0.125)
    float qreg[16];
    {
        const float* qp = g_qkv + (size_t)(b * Tc + t) * (3 * Ec) + h * 64 + sub * 16;
        #pragma unroll
        for (int i = 0; i < 16; i++) qreg[i] = qp[i] * 0.125f;
    }

    float m = -INFINITY, lsum = 0.f;
    float acc[16];
    #pragma unroll
    for (int i = 0; i < 16; i++) acc[i] = 0.f;

    for (int kt = 0; kt <= qt; kt++) {
        __syncthreads();
        #pragma unroll
        for (int p = 0; p < 4; p++) {
            int fid = p * 256 + tid;            // 0..1023
            int j = fid >> 4;
            int d4 = (fid & 15) * 4;
            size_t src = (size_t)(b * Tc + kt * 64 + j) * (3 * Ec) + Ec + h * 64 + d4;
            *(float4*)&sK[j][d4] = *(const float4*)&g_qkv[src];
            *(float4*)&sV[j][d4] = *(const float4*)&g_qkv[src + Ec];
        }
        __syncthreads();

        const bool diag = (kt == qt);
        for (int j0 = 0; j0 < 64; j0 += 8) {
            float s[8];
            #pragma unroll
            for (int jj = 0; jj < 8; jj++) {
                int j = j0 + jj;
                float partial = 0.f;
                #pragma unroll
                for (int i = 0; i < 16; i += 4) {
                    float4 kv = *(float4*)&sK[j][sub * 16 + i];
                    partial += qreg[i] * kv.x + qreg[i+1] * kv.y
                             + qreg[i+2] * kv.z + qreg[i+3] * kv.w;
                }
                partial += __shfl_xor_sync(0xffffffffu, partial, 1);
                partial += __shfl_xor_sync(0xffffffffu, partial, 2);
                s[jj] = partial;
            }
            if (diag) {
                #pragma unroll
                for (int jj = 0; jj < 8; jj++)
                    if (j0 + jj > qid) s[jj] = -INFINITY;
            }
            float cm = s[0];
            #pragma unroll
            for (int jj = 1; jj < 8; jj++) cm = fmaxf(cm, s[jj]);
            float mnew = fmaxf(m, cm);
            if (mnew == -INFINITY) continue;    // fully-masked chunk (uniform per sub-group)
            float corr = __expf(m - mnew);      // exp(-inf)=0 on first live chunk
            lsum *= corr;
            #pragma unroll
            for (int i = 0; i < 16; i++) acc[i] *= corr;
            #pragma unroll
            for (int jj = 0; jj < 8; jj++) {
                float pexp = __expf(s[jj] - mnew);
                lsum += pexp;
                #pragma unroll
                for (int i = 0; i < 16; i += 4) {
                    float4 vv = *(float4*)&sV[j0 + jj][sub * 16 + i];
                    acc[i]   += pexp * vv.x;
                    acc[i+1] += pexp * vv.y;
                    acc[i+2] += pexp * vv.z;
                    acc[i+3] += pexp * vv.w;
                }
            }
            m = mnew;
        }
    }

    float inv = 1.0f / lsum;
    float* op = g_att + (size_t)(b * Tc + t) * Ec + h * 64 + sub * 16;
    #pragma unroll
    for (int i = 0; i < 16; i++) op[i] = acc[i] * inv;
}

// ---------------- per-row loss: log-softmax over V, gather target ----------------
__global__ void rowloss_kernel(const float* __restrict__ logits,
                               const int* __restrict__ targets) {
    int row = blockIdx.x;
    int tid = threadIdx.x;
    const float* lr = logits + (size_t)row * Vc;

    __shared__ float red1[8], red2[8];
    __shared__ float smx;

    float mx = -INFINITY;
    for (int i = tid; i < Vc; i += 256) mx = fmaxf(mx, lr[i]);
    #pragma unroll
    for (int o = 16; o; o >>= 1) mx = fmaxf(mx, __shfl_xor_sync(0xffffffffu, mx, o));
    if ((tid & 31) == 0) red1[tid >> 5] = mx;
    __syncthreads();
    if (tid == 0) {
        float v = red1[0];
        #pragma unroll
        for (int w = 1; w < 8; w++) v = fmaxf(v, red1[w]);
        smx = v;
    }
    __syncthreads();
    mx = smx;

    float se = 0.f;
    for (int i = tid; i < Vc; i += 256) se += __expf(lr[i] - mx);
    #pragma unroll
    for (int o = 16; o; o >>= 1) se += __shfl_xor_sync(0xffffffffu, se, o);
    if ((tid & 31) == 0) red2[tid >> 5] = se;
    __syncthreads();
    if (tid == 0) {
        float tot = 0.f;
        #pragma unroll
        for (int w = 0; w < 8; w++) tot += red2[w];
        int tg = targets[row];
        g_rowloss[row] = logf(tot) + mx - lr[tg];
    }
}

__global__ void loss_reduce_kernel(float* __restrict__ out) {
    int tid = threadIdx.x;
    __shared__ float red[8];
    float s = 0.f;
    for (int i = tid; i < Mc; i += 256) s += g_rowloss[i];
    #pragma unroll
    for (int o = 16; o; o >>= 1) s += __shfl_xor_sync(0xffffffffu, s, o);
    if ((tid & 31) == 0) red[tid >> 5] = s;
    __syncthreads();
    if (tid == 0) {
        float tot = 0.f;
        #pragma unroll
        for (int w = 0; w < 8; w++) tot += red[w];
        out[0] = tot / (float)Mc;
    }
}

// ---------------- host driver ----------------
extern "C" void kernel_launch(void* const* d_in, const int* in_sizes, int n_in,
                              void* d_out, int out_size) {
    (void)in_sizes; (void)n_in;
    const int*   idx     = (const int*)  d_in[0];
    const int*   targets = (const int*)  d_in[1];
    const float* tok_emb = (const float*)d_in[2];
    const float* pos_emb = (const float*)d_in[3];
    const float* Wq      = (const float*)d_in[4];
    const float* Wk      = (const float*)d_in[5];
    const float* Wv      = (const float*)d_in[6];
    const float* Wproj   = (const float*)d_in[7];
    const float* bproj   = (const float*)d_in[8];
    const float* ln1_g   = (const float*)d_in[9];
    const float* ln1_b   = (const float*)d_in[10];
    const float* ln2_g   = (const float*)d_in[11];
    const float* ln2_b   = (const float*)d_in[12];
    const float* W1      = (const float*)d_in[13];
    const float* b1      = (const float*)d_in[14];
    const float* W2      = (const float*)d_in[15];
    const float* b2      = (const float*)d_in[16];
    const float* lnf_g   = (const float*)d_in[17];
    const float* lnf_b   = (const float*)d_in[18];
    const float* Whead   = (const float*)d_in[19];
    const float* bhead   = (const float*)d_in[20];

    float *xp, *hp, *wtp, *qkvp, *attp, *fp, *lgp;
    cudaGetSymbolAddress((void**)&xp,   g_x);
    cudaGetSymbolAddress((void**)&hp,   g_h);
    cudaGetSymbolAddress((void**)&wtp,  g_wt);
    cudaGetSymbolAddress((void**)&qkvp, g_qkv);
    cudaGetSymbolAddress((void**)&attp, g_att);
    cudaGetSymbolAddress((void**)&fp,   g_f);
    cudaGetSymbolAddress((void**)&lgp,  g_logits);

    embed_kernel<<<Mc, 256>>>(idx, tok_emb, pos_emb);

    for (int l = 0; l < Lc; l++) {
        ln_kernel<<<Mc, 256>>>(xp, hp, ln1_g + (size_t)l * Ec, ln1_b + (size_t)l * Ec);
        rearrange_kernel<<<(3 * Ec * Ec) / 256, 256>>>(Wq, Wk, Wv, l);
        sgemm<false, false, false><<<dim3(3 * Ec / 128, Mc / 128), 256>>>(
            hp, wtp, (const float*)nullptr, qkvp, Mc, 3 * Ec, Ec);
        attn_kernel<<<dim3(Tc / 64, Hc, Bc), 256>>>();
        sgemm<true, false, true><<<dim3(Ec / 128, Mc / 128), 256>>>(
            attp, Wproj + (size_t)l * Ec * Ec, bproj + (size_t)l * Ec, xp, Mc, Ec, Ec);
        ln_kernel<<<Mc, 256>>>(xp, hp, ln2_g + (size_t)l * Ec, ln2_b + (size_t)l * Ec);
        sgemm<true, true, false><<<dim3(FFc / 128, Mc / 128), 256>>>(
            hp, W1 + (size_t)l * Ec * FFc, b1 + (size_t)l * FFc, fp, Mc, FFc, Ec);
        sgemm<true, false, true><<<dim3(Ec / 128, Mc / 128), 256>>>(
            fp, W2 + (size_t)l * FFc * Ec, b2 + (size_t)l * Ec, xp, Mc, Ec, FFc);
    }

    ln_kernel<<<Mc, 256>>>(xp, hp, lnf_g, lnf_b);

    const size_t MV = (size_t)Mc * Vc;
    float* logits;
    float* lossptr = nullptr;
    if ((size_t)out_size >= MV) {
        logits = (float*)d_out;
        if ((size_t)out_size > MV) lossptr = (float*)d_out + MV;
    } else {
        logits = lgp;               // loss-only output
        lossptr = (float*)d_out;
    }

    sgemm<true, false, false><<<dim3(Vc / 128, Mc / 128), 256>>>(
        hp, Whead, bhead, logits, Mc, Vc, Ec);

    if (lossptr) {
        rowloss_kernel<<<Mc, 256>>>(logits, targets);
        loss_reduce_kernel<<<1, 256>>>(lossptr);
    }
}

// round 12
// speedup vs baseline: 1.4501x; 1.4501x over previous
#include <cuda_runtime.h>
#include <cuda_bf16.h>
#include <math.h>
#include <stdint.h>

// ---------------- problem constants ----------------
#define Bc   2
#define Tc   2048
#define Ec   1024
#define Hc   16
#define HDc  64
#define Lc   4
#define Vc   32000
#define FFc  4096
#define Mc   (Bc*Tc)      // 4096
#define EPSc 1e-5f

// ---------------- device scratch (static; allocation-free) ----------------
__device__ float g_x[Mc*Ec];                     // residual stream
__device__ float g_h[Mc*Ec];                     // layernorm output
__device__ float g_wt[Ec*3*Ec];                  // rearranged QKV weight [E, 3E] fp32
__device__ float g_qkv[Mc*3*Ec];                 // [B,T,{q,k,v},H,HD]
__device__ float g_att[Mc*Ec];                   // attention out, head-concat layout
__device__ float g_f[(size_t)Mc*FFc];            // MLP hidden
__device__ float g_logits[(size_t)Mc*Vc];        // fallback logits if d_out too small
__device__ float g_rowloss[Mc];
// bf16 split buffers:  A3 = [Ah, Ah, Al] along K;  B3 = [Bh, Bl, Bh] along K (B transposed)
__device__ __nv_bfloat16 g_a3[(size_t)Mc * 3 * FFc];   // max M x 3*4096
__device__ __nv_bfloat16 g_b3[(size_t)Vc * 3 * Ec];    // max 32000 x 3*1024

// ============================================================================
// helpers
// ============================================================================
__device__ __forceinline__ uint32_t smem_u32(const void* p) {
    return (uint32_t)__cvta_generic_to_shared(p);
}

__device__ __forceinline__ void ldsm_x4(uint32_t& r0, uint32_t& r1,
                                        uint32_t& r2, uint32_t& r3, uint32_t addr) {
    asm volatile("ldmatrix.sync.aligned.m8n8.x4.shared.b16 {%0,%1,%2,%3}, [%4];"
                 : "=r"(r0), "=r"(r1), "=r"(r2), "=r"(r3) : "r"(addr));
}

__device__ __forceinline__ void mma16816(float* c, const uint32_t* a, const uint32_t* b) {
    asm volatile(
        "mma.sync.aligned.m16n8k16.row.col.f32.bf16.bf16.f32 "
        "{%0,%1,%2,%3}, {%4,%5,%6,%7}, {%8,%9}, {%0,%1,%2,%3};"
        : "+f"(c[0]), "+f"(c[1]), "+f"(c[2]), "+f"(c[3])
        : "r"(a[0]), "r"(a[1]), "r"(a[2]), "r"(a[3]), "r"(b[0]), "r"(b[1]));
}

// ============================================================================
// bf16 HMMA GEMM: C[M,N] = A3[M,K3] * B3[N,K3]^T (+bias)(relu)(+=C)
// BM=128, BN=128, BK=32, 256 threads (8 warps, 2x4), warp tile 64x32.
// smem row stride 40 bf16 (80B) -> conflict-free ldmatrix.
// ============================================================================
#define SROW 40
#define SBUF (128*SROW)

template<bool BIAS, bool RELU, bool RESID>
__global__ void __launch_bounds__(256, 2)
hgemm(const __nv_bfloat16* __restrict__ A3, const __nv_bfloat16* __restrict__ B3,
      const float* __restrict__ bias, float* __restrict__ C, int Ndim, int K3) {
    __shared__ __nv_bfloat16 As[2][SBUF];
    __shared__ __nv_bfloat16 Bs[2][SBUF];

    const int tid  = threadIdx.x;
    const int wid  = tid >> 5, lane = tid & 31;
    const int wm   = (wid & 1) * 64;     // warp M offset in tile
    const int wn   = (wid >> 1) * 32;    // warp N offset in tile
    const int brow0 = blockIdx.y * 128, bcol0 = blockIdx.x * 128;

    const __nv_bfloat16* Ag = A3 + (size_t)brow0 * K3;
    const __nv_bfloat16* Bg = B3 + (size_t)bcol0 * K3;

    float acc[4][4][4];
    #pragma unroll
    for (int i = 0; i < 4; i++)
        #pragma unroll
        for (int j = 0; j < 4; j++)
            #pragma unroll
            for (int k = 0; k < 4; k++) acc[i][j][k] = 0.f;

    // global-load coordinates: 512 16B-chunks per operand, 2 per thread
    const int gr0 = tid >> 2;                 // row for chunk 0 (0..63)
    const int gc0 = (tid & 3) * 8;            // bf16 col offset
    // chunk 1: row gr0+64, same col

    // ldmatrix smem base addresses (bytes)
    // A: lanes 0-15 rows m..m+15 (k-half 0), lanes 16-31 same rows (k-half 8)
    const uint32_t aBase = smem_u32(&As[0][0]) +
        (uint32_t)(((wm + (lane & 15)) * SROW + ((lane >> 4) << 3)) * 2);
    // B: lane groups (0-7,8-15,16-23,24-31) -> (n0-7,k0),(n0-7,k8),(n8-15,k0),(n8-15,k8)
    const uint32_t bBase = smem_u32(&Bs[0][0]) +
        (uint32_t)(((wn + ((lane >> 4) << 3) + (lane & 7)) * SROW + (((lane >> 3) & 1) << 3)) * 2);

    const int KT = K3 >> 5;

    // prefetch tile 0
    {
        *(float4*)&As[0][gr0 * SROW + gc0] = *(const float4*)&Ag[(size_t)gr0 * K3 + gc0];
        *(float4*)&As[0][(gr0 + 64) * SROW + gc0] = *(const float4*)&Ag[(size_t)(gr0 + 64) * K3 + gc0];
        *(float4*)&Bs[0][gr0 * SROW + gc0] = *(const float4*)&Bg[(size_t)gr0 * K3 + gc0];
        *(float4*)&Bs[0][(gr0 + 64) * SROW + gc0] = *(const float4*)&Bg[(size_t)(gr0 + 64) * K3 + gc0];
    }
    __syncthreads();

    for (int kt = 0; kt < KT; kt++) {
        const int buf = kt & 1;
        float4 ra0, ra1, rb0, rb1;
        if (kt + 1 < KT) {
            const size_t koff = (size_t)(kt + 1) * 32;
            ra0 = *(const float4*)&Ag[(size_t)gr0 * K3 + koff + gc0];
            ra1 = *(const float4*)&Ag[(size_t)(gr0 + 64) * K3 + koff + gc0];
            rb0 = *(const float4*)&Bg[(size_t)gr0 * K3 + koff + gc0];
            rb1 = *(const float4*)&Bg[(size_t)(gr0 + 64) * K3 + koff + gc0];
        }

        const uint32_t ab = aBase + (uint32_t)buf * (SBUF * 2);
        const uint32_t bb = bBase + (uint32_t)buf * (SBUF * 2);
        #pragma unroll
        for (int ks = 0; ks < 2; ks++) {
            uint32_t a[4][4], b[4][2];
            #pragma unroll
            for (int mi = 0; mi < 4; mi++)
                ldsm_x4(a[mi][0], a[mi][1], a[mi][2], a[mi][3],
                        ab + mi * (16 * SROW * 2) + ks * 32);
            #pragma unroll
            for (int nj = 0; nj < 2; nj++)
                ldsm_x4(b[2*nj][0], b[2*nj][1], b[2*nj+1][0], b[2*nj+1][1],
                        bb + nj * (16 * SROW * 2) + ks * 32);
            #pragma unroll
            for (int mi = 0; mi < 4; mi++)
                #pragma unroll
                for (int ni = 0; ni < 4; ni++)
                    mma16816(acc[mi][ni], a[mi], b[ni]);
        }

        if (kt + 1 < KT) {
            const int nb = buf ^ 1;
            *(float4*)&As[nb][gr0 * SROW + gc0] = ra0;
            *(float4*)&As[nb][(gr0 + 64) * SROW + gc0] = ra1;
            *(float4*)&Bs[nb][gr0 * SROW + gc0] = rb0;
            *(float4*)&Bs[nb][(gr0 + 64) * SROW + gc0] = rb1;
            __syncthreads();
        }
    }

    // epilogue: fragment layout c0,c1 -> (row=lane>>2, col=2*(lane&3)+{0,1}); c2,c3 -> row+8
    const int erow = lane >> 2;
    const int ecol = (lane & 3) * 2;
    #pragma unroll
    for (int mi = 0; mi < 4; mi++) {
        #pragma unroll
        for (int ni = 0; ni < 4; ni++) {
            const int col = bcol0 + wn + ni * 8 + ecol;
            float bx = 0.f, by = 0.f;
            if (BIAS) { bx = bias[col]; by = bias[col + 1]; }
            #pragma unroll
            for (int half = 0; half < 2; half++) {
                const int row = brow0 + wm + mi * 16 + erow + half * 8;
                float v0 = acc[mi][ni][half * 2 + 0];
                float v1 = acc[mi][ni][half * 2 + 1];
                if (BIAS) { v0 += bx; v1 += by; }
                if (RELU) { v0 = fmaxf(v0, 0.f); v1 = fmaxf(v1, 0.f); }
                float* cp = C + (size_t)row * Ndim + col;
                if (RESID) {
                    float2 o = *(float2*)cp;
                    v0 += o.x; v1 += o.y;
                }
                *(float2*)cp = make_float2(v0, v1);
            }
        }
    }
}

// ============================================================================
// fp32 -> bf16 split conversions
// ============================================================================
// A[M,K] fp32 -> A3[M,3K] = [Ah, Ah, Al]
__global__ void convA_kernel(const float* __restrict__ A, __nv_bfloat16* __restrict__ A3,
                             int Kdim) {
    size_t i4 = (size_t)blockIdx.x * 256 + threadIdx.x;   // float4 index
    int K4 = Kdim >> 2;
    size_t m = i4 / K4;
    int k = (int)(i4 - m * (size_t)K4) << 2;
    float4 v = *(const float4*)(A + m * (size_t)Kdim + k);
    float f[4] = {v.x, v.y, v.z, v.w};
    ushort4 hs, ls;
    unsigned short* hp = (unsigned short*)&hs;
    unsigned short* lp = (unsigned short*)&ls;
    #pragma unroll
    for (int j = 0; j < 4; j++) {
        __nv_bfloat16 h = __float2bfloat16(f[j]);
        __nv_bfloat16 l = __float2bfloat16(f[j] - __bfloat162float(h));
        hp[j] = __bfloat16_as_ushort(h);
        lp[j] = __bfloat16_as_ushort(l);
    }
    size_t base = m * (size_t)(3 * Kdim) + k;
    *(ushort4*)(A3 + base)            = hs;
    *(ushort4*)(A3 + base + Kdim)     = hs;
    *(ushort4*)(A3 + base + 2 * Kdim) = ls;
}

// W[K,N] fp32 -> B3[N,3K] = [Bh, Bl, Bh] (transposed)
__global__ void convB_kernel(const float* __restrict__ W, __nv_bfloat16* __restrict__ B3,
                             int Kdim, int Ndim) {
    __shared__ float tile[32][33];
    int n0 = blockIdx.x * 32, k0 = blockIdx.y * 32;
    int tx = threadIdx.x, ty = threadIdx.y;   // block (32, 8)
    #pragma unroll
    for (int i = 0; i < 4; i++)
        tile[ty + 8 * i][tx] = W[(size_t)(k0 + ty + 8 * i) * Ndim + n0 + tx];
    __syncthreads();
    #pragma unroll
    for (int i = 0; i < 4; i++) {
        float x = tile[tx][ty + 8 * i];
        __nv_bfloat16 h = __float2bfloat16(x);
        __nv_bfloat16 l = __float2bfloat16(x - __bfloat162float(h));
        size_t r = (size_t)(n0 + ty + 8 * i) * (size_t)(3 * Kdim) + k0 + tx;
        B3[r]            = h;
        B3[r + Kdim]     = l;
        B3[r + 2 * Kdim] = h;
    }
}

// ---------------- embedding ----------------
__global__ void embed_kernel(const int* __restrict__ idx,
                             const float* __restrict__ tok,
                             const float* __restrict__ pos) {
    int row = blockIdx.x;
    int t = row & (Tc - 1);
    int token = idx[row];
    const float4* t4 = (const float4*)(tok + (size_t)token * Ec);
    const float4* p4 = (const float4*)(pos + (size_t)t * Ec);
    float4* o4 = (float4*)(g_x + (size_t)row * Ec);
    int i = threadIdx.x;
    float4 a = t4[i], p = p4[i];
    o4[i] = make_float4(a.x + p.x, a.y + p.y, a.z + p.z, a.w + p.w);
}

// ---------------- layernorm ----------------
__global__ void ln_kernel(const float* __restrict__ in, float* __restrict__ out,
                          const float* __restrict__ gamma, const float* __restrict__ beta) {
    int row = blockIdx.x;
    int tid = threadIdx.x;
    const float4* in4 = (const float4*)(in + (size_t)row * Ec);
    float4 v = in4[tid];
    float s  = v.x + v.y + v.z + v.w;
    float ss = v.x*v.x + v.y*v.y + v.z*v.z + v.w*v.w;

    __shared__ float rs[8], rss[8];
    #pragma unroll
    for (int o = 16; o; o >>= 1) {
        s  += __shfl_xor_sync(0xffffffffu, s,  o);
        ss += __shfl_xor_sync(0xffffffffu, ss, o);
    }
    if ((tid & 31) == 0) { rs[tid >> 5] = s; rss[tid >> 5] = ss; }
    __syncthreads();
    __shared__ float smean, srstd;
    if (tid == 0) {
        float ts = 0.f, tss = 0.f;
        #pragma unroll
        for (int w = 0; w < 8; w++) { ts += rs[w]; tss += rss[w]; }
        float mean = ts * (1.0f / Ec);
        float var  = tss * (1.0f / Ec) - mean * mean;
        smean = mean;
        srstd = rsqrtf(var + EPSc);
    }
    __syncthreads();
    float mean = smean, rstd = srstd;
    float4 g = ((const float4*)gamma)[tid];
    float4 b = ((const float4*)beta)[tid];
    float4 o;
    o.x = (v.x - mean) * rstd * g.x + b.x;
    o.y = (v.y - mean) * rstd * g.y + b.y;
    o.z = (v.z - mean) * rstd * g.z + b.z;
    o.w = (v.w - mean) * rstd * g.w + b.w;
    ((float4*)(out + (size_t)row * Ec))[tid] = o;
}

// ---------------- QKV weight rearrange into [E, 3E] fp32 ----------------
__global__ void rearrange_kernel(const float* __restrict__ Wq,
                                 const float* __restrict__ Wk,
                                 const float* __restrict__ Wv, int l) {
    int i = blockIdx.x * 256 + threadIdx.x;  // 0 .. 3*E*E-1
    int e = i / (3 * Ec);
    int n = i - e * (3 * Ec);
    int which = n >> 10;
    int c = n & 1023;
    const float* W = (which == 0) ? Wq : (which == 1 ? Wk : Wv);
    g_wt[i] = W[(((size_t)l * Hc + (c >> 6)) * Ec + e) * HDc + (c & 63)];
}

// ---------------- causal flash attention (fp32) ----------------
__global__ void __launch_bounds__(256, 2) attn_kernel() {
    const int qt = blockIdx.x, h = blockIdx.y, b = blockIdx.z;
    const int tid = threadIdx.x;
    const int qid = tid >> 2;
    const int sub = tid & 3;
    const int t = qt * 64 + qid;

    __shared__ float sK[64][64];
    __shared__ float sV[64][64];

    float qreg[16];
    {
        const float* qp = g_qkv + (size_t)(b * Tc + t) * (3 * Ec) + h * 64 + sub * 16;
        #pragma unroll
        for (int i = 0; i < 16; i++) qreg[i] = qp[i] * 0.125f;
    }

    float m = -INFINITY, lsum = 0.f;
    float acc[16];
    #pragma unroll
    for (int i = 0; i < 16; i++) acc[i] = 0.f;

    for (int kt = 0; kt <= qt; kt++) {
        __syncthreads();
        #pragma unroll
        for (int p = 0; p < 4; p++) {
            int fid = p * 256 + tid;
            int j = fid >> 4;
            int d4 = (fid & 15) * 4;
            size_t src = (size_t)(b * Tc + kt * 64 + j) * (3 * Ec) + Ec + h * 64 + d4;
            *(float4*)&sK[j][d4] = *(const float4*)&g_qkv[src];
            *(float4*)&sV[j][d4] = *(const float4*)&g_qkv[src + Ec];
        }
        __syncthreads();

        const bool diag = (kt == qt);
        for (int j0 = 0; j0 < 64; j0 += 8) {
            float s[8];
            #pragma unroll
            for (int jj = 0; jj < 8; jj++) {
                int j = j0 + jj;
                float partial = 0.f;
                #pragma unroll
                for (int i = 0; i < 16; i += 4) {
                    float4 kv = *(float4*)&sK[j][sub * 16 + i];
                    partial += qreg[i] * kv.x + qreg[i+1] * kv.y
                             + qreg[i+2] * kv.z + qreg[i+3] * kv.w;
                }
                partial += __shfl_xor_sync(0xffffffffu, partial, 1);
                partial += __shfl_xor_sync(0xffffffffu, partial, 2);
                s[jj] = partial;
            }
            if (diag) {
                #pragma unroll
                for (int jj = 0; jj < 8; jj++)
                    if (j0 + jj > qid) s[jj] = -INFINITY;
            }
            float cm = s[0];
            #pragma unroll
            for (int jj = 1; jj < 8; jj++) cm = fmaxf(cm, s[jj]);
            float mnew = fmaxf(m, cm);
            if (mnew == -INFINITY) continue;
            float corr = __expf(m - mnew);
            lsum *= corr;
            #pragma unroll
            for (int i = 0; i < 16; i++) acc[i] *= corr;
            #pragma unroll
            for (int jj = 0; jj < 8; jj++) {
                float pexp = __expf(s[jj] - mnew);
                lsum += pexp;
                #pragma unroll
                for (int i = 0; i < 16; i += 4) {
                    float4 vv = *(float4*)&sV[j0 + jj][sub * 16 + i];
                    acc[i]   += pexp * vv.x;
                    acc[i+1] += pexp * vv.y;
                    acc[i+2] += pexp * vv.z;
                    acc[i+3] += pexp * vv.w;
                }
            }
            m = mnew;
        }
    }

    float inv = 1.0f / lsum;
    float* op = g_att + (size_t)(b * Tc + t) * Ec + h * 64 + sub * 16;
    #pragma unroll
    for (int i = 0; i < 16; i++) op[i] = acc[i] * inv;
}

// ---------------- loss ----------------
__global__ void rowloss_kernel(const float* __restrict__ logits,
                               const int* __restrict__ targets) {
    int row = blockIdx.x;
    int tid = threadIdx.x;
    const float* lr = logits + (size_t)row * Vc;

    __shared__ float red1[8], red2[8];
    __shared__ float smx;

    float mx = -INFINITY;
    for (int i = tid; i < Vc; i += 256) mx = fmaxf(mx, lr[i]);
    #pragma unroll
    for (int o = 16; o; o >>= 1) mx = fmaxf(mx, __shfl_xor_sync(0xffffffffu, mx, o));
    if ((tid & 31) == 0) red1[tid >> 5] = mx;
    __syncthreads();
    if (tid == 0) {
        float v = red1[0];
        #pragma unroll
        for (int w = 1; w < 8; w++) v = fmaxf(v, red1[w]);
        smx = v;
    }
    __syncthreads();
    mx = smx;

    float se = 0.f;
    for (int i = tid; i < Vc; i += 256) se += __expf(lr[i] - mx);
    #pragma unroll
    for (int o = 16; o; o >>= 1) se += __shfl_xor_sync(0xffffffffu, se, o);
    if ((tid & 31) == 0) red2[tid >> 5] = se;
    __syncthreads();
    if (tid == 0) {
        float tot = 0.f;
        #pragma unroll
        for (int w = 0; w < 8; w++) tot += red2[w];
        int tg = targets[row];
        g_rowloss[row] = logf(tot) + mx - lr[tg];
    }
}

__global__ void loss_reduce_kernel(float* __restrict__ out) {
    int tid = threadIdx.x;
    __shared__ float red[8];
    float s = 0.f;
    for (int i = tid; i < Mc; i += 256) s += g_rowloss[i];
    #pragma unroll
    for (int o = 16; o; o >>= 1) s += __shfl_xor_sync(0xffffffffu, s, o);
    if ((tid & 31) == 0) red[tid >> 5] = s;
    __syncthreads();
    if (tid == 0) {
        float tot = 0.f;
        #pragma unroll
        for (int w = 0; w < 8; w++) tot += red[w];
        out[0] = tot / (float)Mc;
    }
}

// ---------------- host driver ----------------
extern "C" void kernel_launch(void* const* d_in, const int* in_sizes, int n_in,
                              void* d_out, int out_size) {
    (void)in_sizes; (void)n_in;
    const int*   idx     = (const int*)  d_in[0];
    const int*   targets = (const int*)  d_in[1];
    const float* tok_emb = (const float*)d_in[2];
    const float* pos_emb = (const float*)d_in[3];
    const float* Wq      = (const float*)d_in[4];
    const float* Wk      = (const float*)d_in[5];
    const float* Wv      = (const float*)d_in[6];
    const float* Wproj   = (const float*)d_in[7];
    const float* bproj   = (const float*)d_in[8];
    const float* ln1_g   = (const float*)d_in[9];
    const float* ln1_b   = (const float*)d_in[10];
    const float* ln2_g   = (const float*)d_in[11];
    const float* ln2_b   = (const float*)d_in[12];
    const float* W1      = (const float*)d_in[13];
    const float* b1      = (const float*)d_in[14];
    const float* W2      = (const float*)d_in[15];
    const float* b2      = (const float*)d_in[16];
    const float* lnf_g   = (const float*)d_in[17];
    const float* lnf_b   = (const float*)d_in[18];
    const float* Whead   = (const float*)d_in[19];
    const float* bhead   = (const float*)d_in[20];

    float *xp, *hp, *wtp, *qkvp, *attp, *fp, *lgp;
    __nv_bfloat16 *a3p, *b3p;
    cudaGetSymbolAddress((void**)&xp,   g_x);
    cudaGetSymbolAddress((void**)&hp,   g_h);
    cudaGetSymbolAddress((void**)&wtp,  g_wt);
    cudaGetSymbolAddress((void**)&qkvp, g_qkv);
    cudaGetSymbolAddress((void**)&attp, g_att);
    cudaGetSymbolAddress((void**)&fp,   g_f);
    cudaGetSymbolAddress((void**)&lgp,  g_logits);
    cudaGetSymbolAddress((void**)&a3p,  g_a3);
    cudaGetSymbolAddress((void**)&b3p,  g_b3);

    embed_kernel<<<Mc, 256>>>(idx, tok_emb, pos_emb);

    const dim3 cblk(32, 8);

    for (int l = 0; l < Lc; l++) {
        // ---- attention block ----
        ln_kernel<<<Mc, 256>>>(xp, hp, ln1_g + (size_t)l * Ec, ln1_b + (size_t)l * Ec);
        convA_kernel<<<(Mc * Ec) / 1024, 256>>>(hp, a3p, Ec);
        rearrange_kernel<<<(3 * Ec * Ec) / 256, 256>>>(Wq, Wk, Wv, l);
        convB_kernel<<<dim3(3 * Ec / 32, Ec / 32), cblk>>>(wtp, b3p, Ec, 3 * Ec);
        hgemm<false, false, false><<<dim3(3 * Ec / 128, Mc / 128), 256>>>(
            a3p, b3p, (const float*)nullptr, qkvp, 3 * Ec, 3 * Ec);
        attn_kernel<<<dim3(Tc / 64, Hc, Bc), 256>>>();
        convA_kernel<<<(Mc * Ec) / 1024, 256>>>(attp, a3p, Ec);
        convB_kernel<<<dim3(Ec / 32, Ec / 32), cblk>>>(
            Wproj + (size_t)l * Ec * Ec, b3p, Ec, Ec);
        hgemm<true, false, true><<<dim3(Ec / 128, Mc / 128), 256>>>(
            a3p, b3p, bproj + (size_t)l * Ec, xp, Ec, 3 * Ec);
        // ---- MLP block ----
        ln_kernel<<<Mc, 256>>>(xp, hp, ln2_g + (size_t)l * Ec, ln2_b + (size_t)l * Ec);
        convA_kernel<<<(Mc * Ec) / 1024, 256>>>(hp, a3p, Ec);
        convB_kernel<<<dim3(FFc / 32, Ec / 32), cblk>>>(
            W1 + (size_t)l * Ec * FFc, b3p, Ec, FFc);
        hgemm<true, true, false><<<dim3(FFc / 128, Mc / 128), 256>>>(
            a3p, b3p, b1 + (size_t)l * FFc, fp, FFc, 3 * Ec);
        convA_kernel<<<((size_t)Mc * FFc) / 1024, 256>>>(fp, a3p, FFc);
        convB_kernel<<<dim3(Ec / 32, FFc / 32), cblk>>>(
            W2 + (size_t)l * FFc * Ec, b3p, FFc, Ec);
        hgemm<true, false, true><<<dim3(Ec / 128, Mc / 128), 256>>>(
            a3p, b3p, b2 + (size_t)l * Ec, xp, Ec, 3 * FFc);
    }

    ln_kernel<<<Mc, 256>>>(xp, hp, lnf_g, lnf_b);

    const size_t MV = (size_t)Mc * Vc;
    float* logits;
    float* lossptr = nullptr;
    if ((size_t)out_size >= MV) {
        logits = (float*)d_out;
        if ((size_t)out_size > MV) lossptr = (float*)d_out + MV;
    } else {
        logits = lgp;
        lossptr = (float*)d_out;
    }

    convA_kernel<<<(Mc * Ec) / 1024, 256>>>(hp, a3p, Ec);
    convB_kernel<<<dim3(Vc / 32, Ec / 32), cblk>>>(Whead, b3p, Ec, Vc);
    hgemm<true, false, false><<<dim3(Vc / 128, Mc / 128), 256>>>(
        a3p, b3p, bhead, logits, Vc, 3 * Ec);

    if (lossptr) {
        rowloss_kernel<<<Mc, 256>>>(logits, targets);
        loss_reduce_kernel<<<1, 256>>>(lossptr);
    }
}

// round 15
// speedup vs baseline: 1.4596x; 1.0065x over previous
#include <cuda_runtime.h>
#include <cuda_bf16.h>
#include <math.h>
#include <stdint.h>

// ---------------- problem constants ----------------
#define Bc   2
#define Tc   2048
#define Ec   1024
#define Hc   16
#define HDc  64
#define Lc   4
#define Vc   32000
#define FFc  4096
#define Mc   (Bc*Tc)      // 4096
#define EPSc 1e-5f

// ---------------- device scratch (static; allocation-free) ----------------
__device__ float g_x[Mc*Ec];                     // residual stream
__device__ float g_h[Mc*Ec];                     // layernorm output
__device__ float g_wt[Ec*3*Ec];                  // rearranged QKV weight [E, 3E] fp32
__device__ float g_qkv[Mc*3*Ec];                 // [B,T,{q,k,v},H,HD]
__device__ float g_att[Mc*Ec];                   // attention out, head-concat layout
__device__ float g_f[(size_t)Mc*FFc];            // MLP hidden
__device__ float g_logits[(size_t)Mc*Vc];        // fallback logits if d_out too small
__device__ float g_rowloss[Mc];
// bf16 split buffers:  A3 = [Ah, Ah, Al] along K;  B3 = [Bh, Bl, Bh] along K (B transposed)
__device__ __nv_bfloat16 g_a3[(size_t)Mc * 3 * FFc];   // max M x 3*4096
__device__ __nv_bfloat16 g_b3[(size_t)Vc * 3 * Ec];    // max 32000 x 3*1024

// ============================================================================
// helpers
// ============================================================================
__device__ __forceinline__ uint32_t smem_u32(const void* p) {
    return (uint32_t)__cvta_generic_to_shared(p);
}

__device__ __forceinline__ void ldsm_x4(uint32_t& r0, uint32_t& r1,
                                        uint32_t& r2, uint32_t& r3, uint32_t addr) {
    asm volatile("ldmatrix.sync.aligned.m8n8.x4.shared.b16 {%0,%1,%2,%3}, [%4];"
                 : "=r"(r0), "=r"(r1), "=r"(r2), "=r"(r3) : "r"(addr));
}

__device__ __forceinline__ void mma16816(float* c, const uint32_t* a, const uint32_t* b) {
    asm volatile(
        "mma.sync.aligned.m16n8k16.row.col.f32.bf16.bf16.f32 "
        "{%0,%1,%2,%3}, {%4,%5,%6,%7}, {%8,%9}, {%0,%1,%2,%3};"
        : "+f"(c[0]), "+f"(c[1]), "+f"(c[2]), "+f"(c[3])
        : "r"(a[0]), "r"(a[1]), "r"(a[2]), "r"(a[3]), "r"(b[0]), "r"(b[1]));
}

// ============================================================================
// bf16 HMMA GEMM: C[M,N] = A3[M,K3] * B3[N,K3]^T (+bias)(relu)(+=C)
// BM=128, BN=128, BK=32, 256 threads (8 warps, 2x4), warp tile 64x32.
// smem row stride 40 bf16 (80B): conflict-free ldmatrix, 16B-aligned for cp.async.
// 4-stage cp.async pipeline. Grid: (M-tiles, N-tiles) -> concurrent CTAs share
// B column tiles (L2 reuse; critical for the V=32000 head GEMM).
// ============================================================================
#define SROW        40
#define STAGE_BYTES (128*SROW*2)       // 10240 B per operand per stage
#define NSTAGE      4
#define AREG_BYTES  (NSTAGE*STAGE_BYTES)  // 40960
#define HG_SMEM     (2*AREG_BYTES)        // 81920

template<bool BIAS, bool RELU, bool RESID>
__global__ void __launch_bounds__(256, 2)
hgemm(const __nv_bfloat16* __restrict__ A3, const __nv_bfloat16* __restrict__ B3,
      const float* __restrict__ bias, float* __restrict__ C, int Ndim, int K3) {
    extern __shared__ char sm[];
    const uint32_t sa = smem_u32(sm);          // A stage region
    const uint32_t sb = sa + AREG_BYTES;       // B stage region

    const int tid  = threadIdx.x;
    const int wid  = tid >> 5, lane = tid & 31;
    const int wm   = (wid & 1) * 64;     // warp M offset in tile
    const int wn   = (wid >> 1) * 32;    // warp N offset in tile
    const int brow0 = blockIdx.x * 128, bcol0 = blockIdx.y * 128;

    const __nv_bfloat16* Ag = A3 + (size_t)brow0 * K3;
    const __nv_bfloat16* Bg = B3 + (size_t)bcol0 * K3;

    float acc[4][4][4];
    #pragma unroll
    for (int i = 0; i < 4; i++)
        #pragma unroll
        for (int j = 0; j < 4; j++)
            #pragma unroll
            for (int k = 0; k < 4; k++) acc[i][j][k] = 0.f;

    // cp.async coordinates: thread t fills row r = t>>1, 16B chunks {c0, c0+1},
    // c0 = (t&1)*2.  (512 chunks per operand per stage, 2+2 per thread.)
    const int gr = tid >> 1;
    const int gcE = (tid & 1) * 16;            // element column of first chunk
    const uint32_t dA = sa + (uint32_t)(gr * 80 + (tid & 1) * 32);
    const uint32_t dB = sb + (uint32_t)(gr * 80 + (tid & 1) * 32);
    const __nv_bfloat16* gA = Ag + (size_t)gr * K3 + gcE;
    const __nv_bfloat16* gB = Bg + (size_t)gr * K3 + gcE;

    // ldmatrix smem offsets within a stage (bytes) — layout identical to R11
    const uint32_t aOff = (uint32_t)(((wm + (lane & 15)) * SROW + ((lane >> 4) << 3)) * 2);
    const uint32_t bOff = (uint32_t)(((wn + ((lane >> 4) << 3) + (lane & 7)) * SROW
                                      + (((lane >> 3) & 1) << 3)) * 2);

    const int KT = K3 >> 5;

    // prologue: stages 0..2
    #pragma unroll
    for (int s = 0; s < NSTAGE - 1; s++) {
        const __nv_bfloat16* pa = gA + (size_t)s * 32;
        const __nv_bfloat16* pb = gB + (size_t)s * 32;
        uint32_t da = dA + s * STAGE_BYTES, db = dB + s * STAGE_BYTES;
        asm volatile("cp.async.cg.shared.global [%0], [%1], 16;" :: "r"(da),      "l"(pa));
        asm volatile("cp.async.cg.shared.global [%0], [%1], 16;" :: "r"(da + 16), "l"(pa + 8));
        asm volatile("cp.async.cg.shared.global [%0], [%1], 16;" :: "r"(db),      "l"(pb));
        asm volatile("cp.async.cg.shared.global [%0], [%1], 16;" :: "r"(db + 16), "l"(pb + 8));
        asm volatile("cp.async.commit_group;");
    }

    for (int kt = 0; kt < KT; kt++) {
        asm volatile("cp.async.wait_group 2;");
        __syncthreads();

        if (kt + NSTAGE - 1 < KT) {
            const int s = (kt + NSTAGE - 1) & (NSTAGE - 1);
            const __nv_bfloat16* pa = gA + (size_t)(kt + NSTAGE - 1) * 32;
            const __nv_bfloat16* pb = gB + (size_t)(kt + NSTAGE - 1) * 32;
            uint32_t da = dA + s * STAGE_BYTES, db = dB + s * STAGE_BYTES;
            asm volatile("cp.async.cg.shared.global [%0], [%1], 16;" :: "r"(da),      "l"(pa));
            asm volatile("cp.async.cg.shared.global [%0], [%1], 16;" :: "r"(da + 16), "l"(pa + 8));
            asm volatile("cp.async.cg.shared.global [%0], [%1], 16;" :: "r"(db),      "l"(pb));
            asm volatile("cp.async.cg.shared.global [%0], [%1], 16;" :: "r"(db + 16), "l"(pb + 8));
        }
        asm volatile("cp.async.commit_group;");

        const int buf = kt & (NSTAGE - 1);
        const uint32_t ab = sa + buf * STAGE_BYTES + aOff;
        const uint32_t bb = sb + buf * STAGE_BYTES + bOff;
        #pragma unroll
        for (int ks = 0; ks < 2; ks++) {
            uint32_t a[4][4], b[4][2];
            #pragma unroll
            for (int mi = 0; mi < 4; mi++)
                ldsm_x4(a[mi][0], a[mi][1], a[mi][2], a[mi][3],
                        ab + mi * (16 * SROW * 2) + ks * 32);
            #pragma unroll
            for (int nj = 0; nj < 2; nj++)
                ldsm_x4(b[2*nj][0], b[2*nj][1], b[2*nj+1][0], b[2*nj+1][1],
                        bb + nj * (16 * SROW * 2) + ks * 32);
            #pragma unroll
            for (int mi = 0; mi < 4; mi++)
                #pragma unroll
                for (int ni = 0; ni < 4; ni++)
                    mma16816(acc[mi][ni], a[mi], b[ni]);
        }
    }
    asm volatile("cp.async.wait_group 0;");

    // epilogue: fragment layout c0,c1 -> (row=lane>>2, col=2*(lane&3)+{0,1}); c2,c3 -> row+8
    const int erow = lane >> 2;
    const int ecol = (lane & 3) * 2;
    #pragma unroll
    for (int mi = 0; mi < 4; mi++) {
        #pragma unroll
        for (int ni = 0; ni < 4; ni++) {
            const int col = bcol0 + wn + ni * 8 + ecol;
            float bx = 0.f, by = 0.f;
            if (BIAS) { bx = bias[col]; by = bias[col + 1]; }
            #pragma unroll
            for (int half = 0; half < 2; half++) {
                const int row = brow0 + wm + mi * 16 + erow + half * 8;
                float v0 = acc[mi][ni][half * 2 + 0];
                float v1 = acc[mi][ni][half * 2 + 1];
                if (BIAS) { v0 += bx; v1 += by; }
                if (RELU) { v0 = fmaxf(v0, 0.f); v1 = fmaxf(v1, 0.f); }
                float* cp = C + (size_t)row * Ndim + col;
                if (RESID) {
                    float2 o = *(float2*)cp;
                    v0 += o.x; v1 += o.y;
                }
                *(float2*)cp = make_float2(v0, v1);
            }
        }
    }
}

// ============================================================================
// fp32 -> bf16 split conversions
// ============================================================================
// A[M,K] fp32 -> A3[M,3K] = [Ah, Ah, Al]
__global__ void convA_kernel(const float* __restrict__ A, __nv_bfloat16* __restrict__ A3,
                             int Kdim) {
    size_t i4 = (size_t)blockIdx.x * 256 + threadIdx.x;   // float4 index
    int K4 = Kdim >> 2;
    size_t m = i4 / K4;
    int k = (int)(i4 - m * (size_t)K4) << 2;
    float4 v = *(const float4*)(A + m * (size_t)Kdim + k);
    float f[4] = {v.x, v.y, v.z, v.w};
    ushort4 hs, ls;
    unsigned short* hp = (unsigned short*)&hs;
    unsigned short* lp = (unsigned short*)&ls;
    #pragma unroll
    for (int j = 0; j < 4; j++) {
        __nv_bfloat16 h = __float2bfloat16(f[j]);
        __nv_bfloat16 l = __float2bfloat16(f[j] - __bfloat162float(h));
        hp[j] = __bfloat16_as_ushort(h);
        lp[j] = __bfloat16_as_ushort(l);
    }
    size_t base = m * (size_t)(3 * Kdim) + k;
    *(ushort4*)(A3 + base)            = hs;
    *(ushort4*)(A3 + base + Kdim)     = hs;
    *(ushort4*)(A3 + base + 2 * Kdim) = ls;
}

// W[K,N] fp32 -> B3[N,3K] = [Bh, Bl, Bh] (transposed)
__global__ void convB_kernel(const float* __restrict__ W, __nv_bfloat16* __restrict__ B3,
                             int Kdim, int Ndim) {
    __shared__ float tile[32][33];
    int n0 = blockIdx.x * 32, k0 = blockIdx.y * 32;
    int tx = threadIdx.x, ty = threadIdx.y;   // block (32, 8)
    #pragma unroll
    for (int i = 0; i < 4; i++)
        tile[ty + 8 * i][tx] = W[(size_t)(k0 + ty + 8 * i) * Ndim + n0 + tx];
    __syncthreads();
    #pragma unroll
    for (int i = 0; i < 4; i++) {
        float x = tile[tx][ty + 8 * i];
        __nv_bfloat16 h = __float2bfloat16(x);
        __nv_bfloat16 l = __float2bfloat16(x - __bfloat162float(h));
        size_t r = (size_t)(n0 + ty + 8 * i) * (size_t)(3 * Kdim) + k0 + tx;
        B3[r]            = h;
        B3[r + Kdim]     = l;
        B3[r + 2 * Kdim] = h;
    }
}

// ---------------- embedding ----------------
__global__ void embed_kernel(const int* __restrict__ idx,
                             const float* __restrict__ tok,
                             const float* __restrict__ pos) {
    int row = blockIdx.x;
    int t = row & (Tc - 1);
    int token = idx[row];
    const float4* t4 = (const float4*)(tok + (size_t)token * Ec);
    const float4* p4 = (const float4*)(pos + (size_t)t * Ec);
    float4* o4 = (float4*)(g_x + (size_t)row * Ec);
    int i = threadIdx.x;
    float4 a = t4[i], p = p4[i];
    o4[i] = make_float4(a.x + p.x, a.y + p.y, a.z + p.z, a.w + p.w);
}

// ---------------- layernorm ----------------
__global__ void ln_kernel(const float* __restrict__ in, float* __restrict__ out,
                          const float* __restrict__ gamma, const float* __restrict__ beta) {
    int row = blockIdx.x;
    int tid = threadIdx.x;
    const float4* in4 = (const float4*)(in + (size_t)row * Ec);
    float4 v = in4[tid];
    float s  = v.x + v.y + v.z + v.w;
    float ss = v.x*v.x + v.y*v.y + v.z*v.z + v.w*v.w;

    __shared__ float rs[8], rss[8];
    #pragma unroll
    for (int o = 16; o; o >>= 1) {
        s  += __shfl_xor_sync(0xffffffffu, s,  o);
        ss += __shfl_xor_sync(0xffffffffu, ss, o);
    }
    if ((tid & 31) == 0) { rs[tid >> 5] = s; rss[tid >> 5] = ss; }
    __syncthreads();
    __shared__ float smean, srstd;
    if (tid == 0) {
        float ts = 0.f, tss = 0.f;
        #pragma unroll
        for (int w = 0; w < 8; w++) { ts += rs[w]; tss += rss[w]; }
        float mean = ts * (1.0f / Ec);
        float var  = tss * (1.0f / Ec) - mean * mean;
        smean = mean;
        srstd = rsqrtf(var + EPSc);
    }
    __syncthreads();
    float mean = smean, rstd = srstd;
    float4 g = ((const float4*)gamma)[tid];
    float4 b = ((const float4*)beta)[tid];
    float4 o;
    o.x = (v.x - mean) * rstd * g.x + b.x;
    o.y = (v.y - mean) * rstd * g.y + b.y;
    o.z = (v.z - mean) * rstd * g.z + b.z;
    o.w = (v.w - mean) * rstd * g.w + b.w;
    ((float4*)(out + (size_t)row * Ec))[tid] = o;
}

// ---------------- QKV weight rearrange into [E, 3E] fp32 ----------------
__global__ void rearrange_kernel(const float* __restrict__ Wq,
                                 const float* __restrict__ Wk,
                                 const float* __restrict__ Wv, int l) {
    int i = blockIdx.x * 256 + threadIdx.x;  // 0 .. 3*E*E-1
    int e = i / (3 * Ec);
    int n = i - e * (3 * Ec);
    int which = n >> 10;
    int c = n & 1023;
    const float* W = (which == 0) ? Wq : (which == 1 ? Wk : Wv);
    g_wt[i] = W[(((size_t)l * Hc + (c >> 6)) * Ec + e) * HDc + (c & 63)];
}

// ---------------- causal flash attention (fp32) ----------------
__global__ void __launch_bounds__(256, 2) attn_kernel() {
    const int qt = blockIdx.x, h = blockIdx.y, b = blockIdx.z;
    const int tid = threadIdx.x;
    const int qid = tid >> 2;
    const int sub = tid & 3;
    const int t = qt * 64 + qid;

    __shared__ float sK[64][64];
    __shared__ float sV[64][64];

    float qreg[16];
    {
        const float* qp = g_qkv + (size_t)(b * Tc + t) * (3 * Ec) + h * 64 + sub * 16;
        #pragma unroll
        for (int i = 0; i < 16; i++) qreg[i] = qp[i] * 0.125f;
    }

    float m = -INFINITY, lsum = 0.f;
    float acc[16];
    #pragma unroll
    for (int i = 0; i < 16; i++) acc[i] = 0.f;

    for (int kt = 0; kt <= qt; kt++) {
        __syncthreads();
        #pragma unroll
        for (int p = 0; p < 4; p++) {
            int fid = p * 256 + tid;
            int j = fid >> 4;
            int d4 = (fid & 15) * 4;
            size_t src = (size_t)(b * Tc + kt * 64 + j) * (3 * Ec) + Ec + h * 64 + d4;
            *(float4*)&sK[j][d4] = *(const float4*)&g_qkv[src];
            *(float4*)&sV[j][d4] = *(const float4*)&g_qkv[src + Ec];
        }
        __syncthreads();

        const bool diag = (kt == qt);
        for (int j0 = 0; j0 < 64; j0 += 8) {
            float s[8];
            #pragma unroll
            for (int jj = 0; jj < 8; jj++) {
                int j = j0 + jj;
                float partial = 0.f;
                #pragma unroll
                for (int i = 0; i < 16; i += 4) {
                    float4 kv = *(float4*)&sK[j][sub * 16 + i];
                    partial += qreg[i] * kv.x + qreg[i+1] * kv.y
                             + qreg[i+2] * kv.z + qreg[i+3] * kv.w;
                }
                partial += __shfl_xor_sync(0xffffffffu, partial, 1);
                partial += __shfl_xor_sync(0xffffffffu, partial, 2);
                s[jj] = partial;
            }
            if (diag) {
                #pragma unroll
                for (int jj = 0; jj < 8; jj++)
                    if (j0 + jj > qid) s[jj] = -INFINITY;
            }
            float cm = s[0];
            #pragma unroll
            for (int jj = 1; jj < 8; jj++) cm = fmaxf(cm, s[jj]);
            float mnew = fmaxf(m, cm);
            if (mnew == -INFINITY) continue;
            float corr = __expf(m - mnew);
            lsum *= corr;
            #pragma unroll
            for (int i = 0; i < 16; i++) acc[i] *= corr;
            #pragma unroll
            for (int jj = 0; jj < 8; jj++) {
                float pexp = __expf(s[jj] - mnew);
                lsum += pexp;
                #pragma unroll
                for (int i = 0; i < 16; i += 4) {
                    float4 vv = *(float4*)&sV[j0 + jj][sub * 16 + i];
                    acc[i]   += pexp * vv.x;
                    acc[i+1] += pexp * vv.y;
                    acc[i+2] += pexp * vv.z;
                    acc[i+3] += pexp * vv.w;
                }
            }
            m = mnew;
        }
    }

    float inv = 1.0f / lsum;
    float* op = g_att + (size_t)(b * Tc + t) * Ec + h * 64 + sub * 16;
    #pragma unroll
    for (int i = 0; i < 16; i++) op[i] = acc[i] * inv;
}

// ---------------- loss ----------------
__global__ void rowloss_kernel(const float* __restrict__ logits,
                               const int* __restrict__ targets) {
    int row = blockIdx.x;
    int tid = threadIdx.x;
    const float* lr = logits + (size_t)row * Vc;

    __shared__ float red1[8], red2[8];
    __shared__ float smx;

    float mx = -INFINITY;
    for (int i = tid; i < Vc; i += 256) mx = fmaxf(mx, lr[i]);
    #pragma unroll
    for (int o = 16; o; o >>= 1) mx = fmaxf(mx, __shfl_xor_sync(0xffffffffu, mx, o));
    if ((tid & 31) == 0) red1[tid >> 5] = mx;
    __syncthreads();
    if (tid == 0) {
        float v = red1[0];
        #pragma unroll
        for (int w = 1; w < 8; w++) v = fmaxf(v, red1[w]);
        smx = v;
    }
    __syncthreads();
    mx = smx;

    float se = 0.f;
    for (int i = tid; i < Vc; i += 256) se += __expf(lr[i] - mx);
    #pragma unroll
    for (int o = 16; o; o >>= 1) se += __shfl_xor_sync(0xffffffffu, se, o);
    if ((tid & 31) == 0) red2[tid >> 5] = se;
    __syncthreads();
    if (tid == 0) {
        float tot = 0.f;
        #pragma unroll
        for (int w = 0; w < 8; w++) tot += red2[w];
        int tg = targets[row];
        g_rowloss[row] = logf(tot) + mx - lr[tg];
    }
}

__global__ void loss_reduce_kernel(float* __restrict__ out) {
    int tid = threadIdx.x;
    __shared__ float red[8];
    float s = 0.f;
    for (int i = tid; i < Mc; i += 256) s += g_rowloss[i];
    #pragma unroll
    for (int o = 16; o; o >>= 1) s += __shfl_xor_sync(0xffffffffu, s, o);
    if ((tid & 31) == 0) red[tid >> 5] = s;
    __syncthreads();
    if (tid == 0) {
        float tot = 0.f;
        #pragma unroll
        for (int w = 0; w < 8; w++) tot += red[w];
        out[0] = tot / (float)Mc;
    }
}

// ---------------- host driver ----------------
extern "C" void kernel_launch(void* const* d_in, const int* in_sizes, int n_in,
                              void* d_out, int out_size) {
    (void)in_sizes; (void)n_in;
    const int*   idx     = (const int*)  d_in[0];
    const int*   targets = (const int*)  d_in[1];
    const float* tok_emb = (const float*)d_in[2];
    const float* pos_emb = (const float*)d_in[3];
    const float* Wq      = (const float*)d_in[4];
    const float* Wk      = (const float*)d_in[5];
    const float* Wv      = (const float*)d_in[6];
    const float* Wproj   = (const float*)d_in[7];
    const float* bproj   = (const float*)d_in[8];
    const float* ln1_g   = (const float*)d_in[9];
    const float* ln1_b   = (const float*)d_in[10];
    const float* ln2_g   = (const float*)d_in[11];
    const float* ln2_b   = (const float*)d_in[12];
    const float* W1      = (const float*)d_in[13];
    const float* b1      = (const float*)d_in[14];
    const float* W2      = (const float*)d_in[15];
    const float* b2      = (const float*)d_in[16];
    const float* lnf_g   = (const float*)d_in[17];
    const float* lnf_b   = (const float*)d_in[18];
    const float* Whead   = (const float*)d_in[19];
    const float* bhead   = (const float*)d_in[20];

    float *xp, *hp, *wtp, *qkvp, *attp, *fp, *lgp;
    __nv_bfloat16 *a3p, *b3p;
    cudaGetSymbolAddress((void**)&xp,   g_x);
    cudaGetSymbolAddress((void**)&hp,   g_h);
    cudaGetSymbolAddress((void**)&wtp,  g_wt);
    cudaGetSymbolAddress((void**)&qkvp, g_qkv);
    cudaGetSymbolAddress((void**)&attp, g_att);
    cudaGetSymbolAddress((void**)&fp,   g_f);
    cudaGetSymbolAddress((void**)&lgp,  g_logits);
    cudaGetSymbolAddress((void**)&a3p,  g_a3);
    cudaGetSymbolAddress((void**)&b3p,  g_b3);

    cudaFuncSetAttribute(hgemm<false, false, false>,
                         cudaFuncAttributeMaxDynamicSharedMemorySize, HG_SMEM);
    cudaFuncSetAttribute(hgemm<true, false, true>,
                         cudaFuncAttributeMaxDynamicSharedMemorySize, HG_SMEM);
    cudaFuncSetAttribute(hgemm<true, true, false>,
                         cudaFuncAttributeMaxDynamicSharedMemorySize, HG_SMEM);
    cudaFuncSetAttribute(hgemm<true, false, false>,
                         cudaFuncAttributeMaxDynamicSharedMemorySize, HG_SMEM);

    embed_kernel<<<Mc, 256>>>(idx, tok_emb, pos_emb);

    const dim3 cblk(32, 8);

    for (int l = 0; l < Lc; l++) {
        // ---- attention block ----
        ln_kernel<<<Mc, 256>>>(xp, hp, ln1_g + (size_t)l * Ec, ln1_b + (size_t)l * Ec);
        convA_kernel<<<(Mc * Ec) / 1024, 256>>>(hp, a3p, Ec);
        rearrange_kernel<<<(3 * Ec * Ec) / 256, 256>>>(Wq, Wk, Wv, l);
        convB_kernel<<<dim3(3 * Ec / 32, Ec / 32), cblk>>>(wtp, b3p, Ec, 3 * Ec);
        hgemm<false, false, false><<<dim3(Mc / 128, 3 * Ec / 128), 256, HG_SMEM>>>(
            a3p, b3p, (const float*)nullptr, qkvp, 3 * Ec, 3 * Ec);
        attn_kernel<<<dim3(Tc / 64, Hc, Bc), 256>>>();
        convA_kernel<<<(Mc * Ec) / 1024, 256>>>(attp, a3p, Ec);
        convB_kernel<<<dim3(Ec / 32, Ec / 32), cblk>>>(
            Wproj + (size_t)l * Ec * Ec, b3p, Ec, Ec);
        hgemm<true, false, true><<<dim3(Mc / 128, Ec / 128), 256, HG_SMEM>>>(
            a3p, b3p, bproj + (size_t)l * Ec, xp, Ec, 3 * Ec);
        // ---- MLP block ----
        ln_kernel<<<Mc, 256>>>(xp, hp, ln2_g + (size_t)l * Ec, ln2_b + (size_t)l * Ec);
        convA_kernel<<<(Mc * Ec) / 1024, 256>>>(hp, a3p, Ec);
        convB_kernel<<<dim3(FFc / 32, Ec / 32), cblk>>>(
            W1 + (size_t)l * Ec * FFc, b3p, Ec, FFc);
        hgemm<true, true, false><<<dim3(Mc / 128, FFc / 128), 256, HG_SMEM>>>(
            a3p, b3p, b1 + (size_t)l * FFc, fp, FFc, 3 * Ec);
        convA_kernel<<<((size_t)Mc * FFc) / 1024, 256>>>(fp, a3p, FFc);
        convB_kernel<<<dim3(Ec / 32, FFc / 32), cblk>>>(
            W2 + (size_t)l * FFc * Ec, b3p, FFc, Ec);
        hgemm<true, false, true><<<dim3(Mc / 128, Ec / 128), 256, HG_SMEM>>>(
            a3p, b3p, b2 + (size_t)l * Ec, xp, Ec, 3 * FFc);
    }

    ln_kernel<<<Mc, 256>>>(xp, hp, lnf_g, lnf_b);

    const size_t MV = (size_t)Mc * Vc;
    float* logits;
    float* lossptr = nullptr;
    if ((size_t)out_size >= MV) {
        logits = (float*)d_out;
        if ((size_t)out_size > MV) lossptr = (float*)d_out + MV;
    } else {
        logits = lgp;
        lossptr = (float*)d_out;
    }

    convA_kernel<<<(Mc * Ec) / 1024, 256>>>(hp, a3p, Ec);
    convB_kernel<<<dim3(Vc / 32, Ec / 32), cblk>>>(Whead, b3p, Ec, Vc);
    hgemm<true, false, false><<<dim3(Mc / 128, Vc / 128), 256, HG_SMEM>>>(
        a3p, b3p, bhead, logits, Vc, 3 * Ec);

    if (lossptr) {
        rowloss_kernel<<<Mc, 256>>>(logits, targets);
        loss_reduce_kernel<<<1, 256>>>(lossptr);
    }
}

// round 17
// speedup vs baseline: 1.6665x; 1.1418x over previous
#include <cuda_runtime.h>
#include <cuda_bf16.h>
#include <math.h>
#include <stdint.h>

// ---------------- problem constants ----------------
#define Bc   2
#define Tc   2048
#define Ec   1024
#define Hc   16
#define HDc  64
#define Lc   4
#define Vc   32000
#define FFc  4096
#define Mc   (Bc*Tc)      // 4096
#define EPSc 1e-5f

// ---------------- device scratch (static; allocation-free) ----------------
__device__ float g_x[Mc*Ec];
__device__ float g_h[Mc*Ec];
__device__ float g_wt[Ec*3*Ec];                  // rearranged QKV weight [E,3E] fp32
__device__ float g_qkv[Mc*3*Ec];                 // [B,T,{q,k,v},H,HD]
__device__ float g_att[Mc*Ec];
__device__ float g_f[(size_t)Mc*FFc];
__device__ float g_logits[(size_t)Mc*Vc];
__device__ float g_rowloss[Mc];
// bf16 split slabs, tiled layout: [K/32][rows][32] with 16B-chunk swizzle
// phys_chunk = (logical_chunk + (row>>1)) & 3
__device__ __nv_bfloat16 g_ah[(size_t)Mc*FFc];   // A hi (max M x 4096)
__device__ __nv_bfloat16 g_al[(size_t)Mc*FFc];   // A lo
__device__ __nv_bfloat16 g_bh[(size_t)Vc*Ec];    // B hi (max 32000 x 1024)
__device__ __nv_bfloat16 g_bl[(size_t)Vc*Ec];    // B lo

// ============================================================================
// helpers
// ============================================================================
__device__ __forceinline__ uint32_t smem_u32(const void* p) {
    return (uint32_t)__cvta_generic_to_shared(p);
}

__device__ __forceinline__ void ldsm_x4(uint32_t& r0, uint32_t& r1,
                                        uint32_t& r2, uint32_t& r3, uint32_t addr) {
    asm volatile("ldmatrix.sync.aligned.m8n8.x4.shared.b16 {%0,%1,%2,%3}, [%4];"
                 : "=r"(r0), "=r"(r1), "=r"(r2), "=r"(r3) : "r"(addr));
}

__device__ __forceinline__ void mma16816(float* c, const uint32_t* a, const uint32_t* b) {
    asm volatile(
        "mma.sync.aligned.m16n8k16.row.col.f32.bf16.bf16.f32 "
        "{%0,%1,%2,%3}, {%4,%5,%6,%7}, {%8,%9}, {%0,%1,%2,%3};"
        : "+f"(c[0]), "+f"(c[1]), "+f"(c[2]), "+f"(c[3])
        : "r"(a[0]), "r"(a[1]), "r"(a[2]), "r"(a[3]), "r"(b[0]), "r"(b[1]));
}

#define MBAR_INIT(a, n) \
    asm volatile("mbarrier.init.shared.b64 [%0], %1;" :: "r"(a), "r"(n) : "memory")
#define MBAR_EXPECT_TX(a, b) \
    asm volatile("mbarrier.arrive.expect_tx.shared.b64 _, [%0], %1;" :: "r"(a), "r"(b) : "memory")
#define MBAR_WAIT(a, ph) do { \
    uint32_t _m = (a), _p = (ph), _d; \
    asm volatile("{\n\t.reg .pred p;\n\t" \
        "mbarrier.try_wait.parity.acquire.cta.shared::cta.b64 p, [%1], %2;\n\t" \
        "selp.b32 %0, 1, 0, p;\n\t}" : "=r"(_d) : "r"(_m), "r"(_p) : "memory"); \
    if (!_d) { \
        asm volatile("{\n\t.reg .pred P1;\n\t" \
            "W_%=:\n\t" \
            "mbarrier.try_wait.parity.acquire.cta.shared::cta.b64 P1, [%0], %1, 0x989680;\n\t" \
            "@P1 bra.uni D_%=;\n\tbra.uni W_%=;\n\tD_%=:\n\t}" \
            :: "r"(_m), "r"(_p) : "memory"); \
    } \
} while (0)

__device__ __forceinline__ void bulk_g2s(uint32_t dst, const void* src,
                                         uint32_t bytes, uint32_t mbar) {
    asm volatile(
        "cp.async.bulk.shared::cluster.global.mbarrier::complete_tx::bytes [%0], [%1], %2, [%3];"
        :: "r"(dst), "l"(src), "r"(bytes), "r"(mbar) : "memory");
}

// ============================================================================
// hgemm2: C[M,N] = (Ah+Al)*(Bh+Bl)^T (3-pass split, bf16 HMMA, fp32 accum)
// BM=256, BN=128, BK=32 base-K. 256 threads, 8 warps (4x2), warp tile 64x64.
// Operands arrive via cp.async.bulk from tiled slabs (contiguous 16KB/8KB per
// K-tile). 4-stage mbarrier pipeline. Fused bias/relu/residual epilogue.
// smem: 4 stages x 48KB = 196608 B + mbarriers.
// ============================================================================
#define STG_BYTES 49152
#define OFF_AH 0
#define OFF_AL 16384
#define OFF_BH 32768
#define OFF_BL 40960
#define NST 4
#define HG2_SMEM (NST*STG_BYTES + 64)

template<bool BIAS, bool RELU, bool RESID>
__global__ void __launch_bounds__(256)
hgemm2(const __nv_bfloat16* __restrict__ Ah, const __nv_bfloat16* __restrict__ Al,
       const __nv_bfloat16* __restrict__ Bh, const __nv_bfloat16* __restrict__ Bl,
       const float* __restrict__ bias, float* __restrict__ C, int Ndim, int Kdim) {
    extern __shared__ char sm[];
    const uint32_t sbase = smem_u32(sm);
    const uint32_t mb = sbase + NST * STG_BYTES;   // 4 mbarriers, 8B each

    const int tid = threadIdx.x;
    const int wid = tid >> 5, lane = tid & 31;
    const int wm = (wid & 3) * 64;      // warp M offset (0..192)
    const int wn = (wid >> 2) * 64;     // warp N offset (0 or 64)
    const int brow0 = blockIdx.x * 256, bcol0 = blockIdx.y * 128;
    const int KT = Kdim >> 5;

    if (tid < NST) MBAR_INIT(mb + tid * 8, 1);
    __syncthreads();

    // slab byte offsets per kt (slabs: [kt][row][32] bf16, chunk-swizzled)
    const char* pAh = (const char*)Ah + (size_t)brow0 * 64;
    const char* pAl = (const char*)Al + (size_t)brow0 * 64;
    const char* pBh = (const char*)Bh + (size_t)bcol0 * 64;
    const char* pBl = (const char*)Bl + (size_t)bcol0 * 64;
    const size_t aStep = (size_t)Mc * 64;          // bytes per kt in A slabs
    const size_t bStep = (size_t)Ndim * 64;        // bytes per kt in B slabs

    if (tid == 0) {
        #pragma unroll
        for (int s = 0; s < NST - 1; s++) {
            uint32_t st = sbase + s * STG_BYTES;
            MBAR_EXPECT_TX(mb + s * 8, (uint32_t)STG_BYTES);
            bulk_g2s(st + OFF_AH, pAh + (size_t)s * aStep, 16384, mb + s * 8);
            bulk_g2s(st + OFF_AL, pAl + (size_t)s * aStep, 16384, mb + s * 8);
            bulk_g2s(st + OFF_BH, pBh + (size_t)s * bStep, 8192,  mb + s * 8);
            bulk_g2s(st + OFF_BL, pBl + (size_t)s * bStep, 8192,  mb + s * 8);
        }
    }

    // ldmatrix addressing (precomputed per-lane; swizzle baked in slab layout)
    // A row: wm + (lane&15) + 16*mi ; chunk c = 2*ks + (lane>>4)
    // B row(n): wn + 16*nj + ((lane>>4)<<3) + (lane&7) ; chunk c = 2*ks + ((lane>>3)&1)
    int aRow6[4], aSw[4], bRow6[4], bSw[4];
    {
        const int l15 = lane & 15, lHi = lane >> 4;
        #pragma unroll
        for (int mi = 0; mi < 4; mi++) {
            int r = wm + l15 + 16 * mi;
            aRow6[mi] = r << 6;                 // row*64 bytes
            aSw[mi] = lHi + (r >> 1);
        }
        const int nl = ((lane >> 4) << 3) + (lane & 7);
        const int kb = (lane >> 3) & 1;
        #pragma unroll
        for (int nj = 0; nj < 4; nj++) {
            int n = wn + 16 * nj + nl;
            bRow6[nj] = n << 6;
            bSw[nj] = kb + (n >> 1);
        }
    }

    float acc[4][8][4];
    #pragma unroll
    for (int i = 0; i < 4; i++)
        #pragma unroll
        for (int j = 0; j < 8; j++)
            #pragma unroll
            for (int k = 0; k < 4; k++) acc[i][j][k] = 0.f;

    for (int kt = 0; kt < KT; kt++) {
        const int s = kt & (NST - 1);
        MBAR_WAIT(mb + s * 8, (kt >> 2) & 1);

        const uint32_t st = sbase + s * STG_BYTES;
        #pragma unroll
        for (int ks = 0; ks < 2; ks++) {
            uint32_t ah[4][4], al[4][4], bh[8][2], bl[8][2];
            #pragma unroll
            for (int mi = 0; mi < 4; mi++) {
                uint32_t sw = (uint32_t)(((2 * ks + aSw[mi]) & 3) << 4);
                ldsm_x4(ah[mi][0], ah[mi][1], ah[mi][2], ah[mi][3],
                        st + OFF_AH + aRow6[mi] + sw);
                ldsm_x4(al[mi][0], al[mi][1], al[mi][2], al[mi][3],
                        st + OFF_AL + aRow6[mi] + sw);
            }
            #pragma unroll
            for (int nj = 0; nj < 4; nj++) {
                uint32_t sw = (uint32_t)(((2 * ks + bSw[nj]) & 3) << 4);
                ldsm_x4(bh[2*nj][0], bh[2*nj][1], bh[2*nj+1][0], bh[2*nj+1][1],
                        st + OFF_BH + bRow6[nj] + sw);
                ldsm_x4(bl[2*nj][0], bl[2*nj][1], bl[2*nj+1][0], bl[2*nj+1][1],
                        st + OFF_BL + bRow6[nj] + sw);
            }
            #pragma unroll
            for (int mi = 0; mi < 4; mi++)
                #pragma unroll
                for (int g = 0; g < 8; g++) {
                    mma16816(acc[mi][g], ah[mi], bh[g]);   // Ah*Bh
                    mma16816(acc[mi][g], ah[mi], bl[g]);   // Ah*Bl
                    mma16816(acc[mi][g], al[mi], bh[g]);   // Al*Bh
                }
        }
        __syncthreads();
        if (tid == 0 && kt + NST - 1 < KT) {
            const int kn = kt + NST - 1;
            const int sn = kn & (NST - 1);
            uint32_t stn = sbase + sn * STG_BYTES;
            MBAR_EXPECT_TX(mb + sn * 8, (uint32_t)STG_BYTES);
            bulk_g2s(stn + OFF_AH, pAh + (size_t)kn * aStep, 16384, mb + sn * 8);
            bulk_g2s(stn + OFF_AL, pAl + (size_t)kn * aStep, 16384, mb + sn * 8);
            bulk_g2s(stn + OFF_BH, pBh + (size_t)kn * bStep, 8192,  mb + sn * 8);
            bulk_g2s(stn + OFF_BL, pBl + (size_t)kn * bStep, 8192,  mb + sn * 8);
        }
    }

    // epilogue: c0,c1 -> (row=lane>>2, col=2*(lane&3)+{0,1}); c2,c3 -> row+8
    const int erow = lane >> 2;
    const int ecol = (lane & 3) * 2;
    #pragma unroll
    for (int mi = 0; mi < 4; mi++) {
        #pragma unroll
        for (int g = 0; g < 8; g++) {
            const int col = bcol0 + wn + g * 8 + ecol;
            float bx = 0.f, by = 0.f;
            if (BIAS) { bx = bias[col]; by = bias[col + 1]; }
            #pragma unroll
            for (int half = 0; half < 2; half++) {
                const int row = brow0 + wm + mi * 16 + erow + half * 8;
                float v0 = acc[mi][g][half * 2 + 0];
                float v1 = acc[mi][g][half * 2 + 1];
                if (BIAS) { v0 += bx; v1 += by; }
                if (RELU) { v0 = fmaxf(v0, 0.f); v1 = fmaxf(v1, 0.f); }
                float* cp = C + (size_t)row * Ndim + col;
                if (RESID) {
                    float2 o = *(float2*)cp;
                    v0 += o.x; v1 += o.y;
                }
                *(float2*)cp = make_float2(v0, v1);
            }
        }
    }
}

// ============================================================================
// conversions into tiled slabs
// ============================================================================
// A[M,K] fp32 -> Ah/Al slabs [K/32][M][32] with chunk swizzle (M = Mc)
__global__ void convA_kernel(const float* __restrict__ A,
                             __nv_bfloat16* __restrict__ Ah,
                             __nv_bfloat16* __restrict__ Al, int Kdim) {
    size_t id = (size_t)blockIdx.x * 256 + threadIdx.x;   // one 16B chunk
    int p = (int)(id & 3);
    int m = (int)((id >> 2) & (Mc - 1));
    int kt = (int)(id >> 14);
    int c = (p - (m >> 1)) & 3;
    const float* src = A + (size_t)m * Kdim + kt * 32 + c * 8;
    float4 v0 = *(const float4*)src;
    float4 v1 = *(const float4*)(src + 4);
    float f[8] = {v0.x, v0.y, v0.z, v0.w, v1.x, v1.y, v1.z, v1.w};
    ushort4 hs[2], ls[2];
    unsigned short* hp = (unsigned short*)hs;
    unsigned short* lp = (unsigned short*)ls;
    #pragma unroll
    for (int j = 0; j < 8; j++) {
        __nv_bfloat16 h = __float2bfloat16(f[j]);
        __nv_bfloat16 l = __float2bfloat16(f[j] - __bfloat162float(h));
        hp[j] = __bfloat16_as_ushort(h);
        lp[j] = __bfloat16_as_ushort(l);
    }
    *(uint4*)(Ah + id * 8) = *(uint4*)hs;
    *(uint4*)(Al + id * 8) = *(uint4*)ls;
}

// W[K,N] fp32 -> Bh/Bl slabs [K/32][N][32] (transposed) with chunk swizzle
__global__ void convB_kernel(const float* __restrict__ W,
                             __nv_bfloat16* __restrict__ Bh,
                             __nv_bfloat16* __restrict__ Bl, int Kdim, int Ndim) {
    __shared__ float tile[32][65];
    const int n0 = blockIdx.x * 64, k0 = blockIdx.y * 32;
    const int t = threadIdx.x;     // 256
    #pragma unroll
    for (int i = 0; i < 8; i++) {
        int e = t + 256 * i;
        int nl = e & 63, kl = e >> 6;
        tile[kl][nl] = W[(size_t)(k0 + kl) * Ndim + n0 + nl];
    }
    __syncthreads();
    const int nl = t >> 2, p = t & 3;
    const int n = n0 + nl;
    const int c = (p - (n >> 1)) & 3;
    ushort4 hs[2], ls[2];
    unsigned short* hp = (unsigned short*)hs;
    unsigned short* lp = (unsigned short*)ls;
    #pragma unroll
    for (int j = 0; j < 8; j++) {
        float x = tile[c * 8 + j][nl];
        __nv_bfloat16 h = __float2bfloat16(x);
        __nv_bfloat16 l = __float2bfloat16(x - __bfloat162float(h));
        hp[j] = __bfloat16_as_ushort(h);
        lp[j] = __bfloat16_as_ushort(l);
    }
    size_t id = ((size_t)(k0 >> 5) * Ndim + n) * 4 + p;
    *(uint4*)(Bh + id * 8) = *(uint4*)hs;
    *(uint4*)(Bl + id * 8) = *(uint4*)ls;
}

// ---------------- embedding ----------------
__global__ void embed_kernel(const int* __restrict__ idx,
                             const float* __restrict__ tok,
                             const float* __restrict__ pos) {
    int row = blockIdx.x;
    int t = row & (Tc - 1);
    int token = idx[row];
    const float4* t4 = (const float4*)(tok + (size_t)token * Ec);
    const float4* p4 = (const float4*)(pos + (size_t)t * Ec);
    float4* o4 = (float4*)(g_x + (size_t)row * Ec);
    int i = threadIdx.x;
    float4 a = t4[i], p = p4[i];
    o4[i] = make_float4(a.x + p.x, a.y + p.y, a.z + p.z, a.w + p.w);
}

// ---------------- layernorm ----------------
__global__ void ln_kernel(const float* __restrict__ in, float* __restrict__ out,
                          const float* __restrict__ gamma, const float* __restrict__ beta) {
    int row = blockIdx.x;
    int tid = threadIdx.x;
    const float4* in4 = (const float4*)(in + (size_t)row * Ec);
    float4 v = in4[tid];
    float s  = v.x + v.y + v.z + v.w;
    float ss = v.x*v.x + v.y*v.y + v.z*v.z + v.w*v.w;

    __shared__ float rs[8], rss[8];
    #pragma unroll
    for (int o = 16; o; o >>= 1) {
        s  += __shfl_xor_sync(0xffffffffu, s,  o);
        ss += __shfl_xor_sync(0xffffffffu, ss, o);
    }
    if ((tid & 31) == 0) { rs[tid >> 5] = s; rss[tid >> 5] = ss; }
    __syncthreads();
    __shared__ float smean, srstd;
    if (tid == 0) {
        float ts = 0.f, tss = 0.f;
        #pragma unroll
        for (int w = 0; w < 8; w++) { ts += rs[w]; tss += rss[w]; }
        float mean = ts * (1.0f / Ec);
        float var  = tss * (1.0f / Ec) - mean * mean;
        smean = mean;
        srstd = rsqrtf(var + EPSc);
    }
    __syncthreads();
    float mean = smean, rstd = srstd;
    float4 g = ((const float4*)gamma)[tid];
    float4 b = ((const float4*)beta)[tid];
    float4 o;
    o.x = (v.x - mean) * rstd * g.x + b.x;
    o.y = (v.y - mean) * rstd * g.y + b.y;
    o.z = (v.z - mean) * rstd * g.z + b.z;
    o.w = (v.w - mean) * rstd * g.w + b.w;
    ((float4*)(out + (size_t)row * Ec))[tid] = o;
}

// ---------------- QKV weight rearrange into [E, 3E] fp32 ----------------
__global__ void rearrange_kernel(const float* __restrict__ Wq,
                                 const float* __restrict__ Wk,
                                 const float* __restrict__ Wv, int l) {
    int i = blockIdx.x * 256 + threadIdx.x;
    int e = i / (3 * Ec);
    int n = i - e * (3 * Ec);
    int which = n >> 10;
    int c = n & 1023;
    const float* W = (which == 0) ? Wq : (which == 1 ? Wk : Wv);
    g_wt[i] = W[(((size_t)l * Hc + (c >> 6)) * Ec + e) * HDc + (c & 63)];
}

// ---------------- causal flash attention (fp32) ----------------
__global__ void __launch_bounds__(256, 2) attn_kernel() {
    const int qt = blockIdx.x, h = blockIdx.y, b = blockIdx.z;
    const int tid = threadIdx.x;
    const int qid = tid >> 2;
    const int sub = tid & 3;
    const int t = qt * 64 + qid;

    __shared__ float sK[64][64];
    __shared__ float sV[64][64];

    float qreg[16];
    {
        const float* qp = g_qkv + (size_t)(b * Tc + t) * (3 * Ec) + h * 64 + sub * 16;
        #pragma unroll
        for (int i = 0; i < 16; i++) qreg[i] = qp[i] * 0.125f;
    }

    float m = -INFINITY, lsum = 0.f;
    float acc[16];
    #pragma unroll
    for (int i = 0; i < 16; i++) acc[i] = 0.f;

    for (int kt = 0; kt <= qt; kt++) {
        __syncthreads();
        #pragma unroll
        for (int p = 0; p < 4; p++) {
            int fid = p * 256 + tid;
            int j = fid >> 4;
            int d4 = (fid & 15) * 4;
            size_t src = (size_t)(b * Tc + kt * 64 + j) * (3 * Ec) + Ec + h * 64 + d4;
            *(float4*)&sK[j][d4] = *(const float4*)&g_qkv[src];
            *(float4*)&sV[j][d4] = *(const float4*)&g_qkv[src + Ec];
        }
        __syncthreads();

        const bool diag = (kt == qt);
        for (int j0 = 0; j0 < 64; j0 += 8) {
            float s[8];
            #pragma unroll
            for (int jj = 0; jj < 8; jj++) {
                int j = j0 + jj;
                float partial = 0.f;
                #pragma unroll
                for (int i = 0; i < 16; i += 4) {
                    float4 kv = *(float4*)&sK[j][sub * 16 + i];
                    partial += qreg[i] * kv.x + qreg[i+1] * kv.y
                             + qreg[i+2] * kv.z + qreg[i+3] * kv.w;
                }
                partial += __shfl_xor_sync(0xffffffffu, partial, 1);
                partial += __shfl_xor_sync(0xffffffffu, partial, 2);
                s[jj] = partial;
            }
            if (diag) {
                #pragma unroll
                for (int jj = 0; jj < 8; jj++)
                    if (j0 + jj > qid) s[jj] = -INFINITY;
            }
            float cm = s[0];
            #pragma unroll
            for (int jj = 1; jj < 8; jj++) cm = fmaxf(cm, s[jj]);
            float mnew = fmaxf(m, cm);
            if (mnew == -INFINITY) continue;
            float corr = __expf(m - mnew);
            lsum *= corr;
            #pragma unroll
            for (int i = 0; i < 16; i++) acc[i] *= corr;
            #pragma unroll
            for (int jj = 0; jj < 8; jj++) {
                float pexp = __expf(s[jj] - mnew);
                lsum += pexp;
                #pragma unroll
                for (int i = 0; i < 16; i += 4) {
                    float4 vv = *(float4*)&sV[j0 + jj][sub * 16 + i];
                    acc[i]   += pexp * vv.x;
                    acc[i+1] += pexp * vv.y;
                    acc[i+2] += pexp * vv.z;
                    acc[i+3] += pexp * vv.w;
                }
            }
            m = mnew;
        }
    }

    float inv = 1.0f / lsum;
    float* op = g_att + (size_t)(b * Tc + t) * Ec + h * 64 + sub * 16;
    #pragma unroll
    for (int i = 0; i < 16; i++) op[i] = acc[i] * inv;
}

// ---------------- loss ----------------
__global__ void rowloss_kernel(const float* __restrict__ logits,
                               const int* __restrict__ targets) {
    int row = blockIdx.x;
    int tid = threadIdx.x;
    const float* lr = logits + (size_t)row * Vc;

    __shared__ float red1[8], red2[8];
    __shared__ float smx;

    float mx = -INFINITY;
    for (int i = tid; i < Vc; i += 256) mx = fmaxf(mx, lr[i]);
    #pragma unroll
    for (int o = 16; o; o >>= 1) mx = fmaxf(mx, __shfl_xor_sync(0xffffffffu, mx, o));
    if ((tid & 31) == 0) red1[tid >> 5] = mx;
    __syncthreads();
    if (tid == 0) {
        float v = red1[0];
        #pragma unroll
        for (int w = 1; w < 8; w++) v = fmaxf(v, red1[w]);
        smx = v;
    }
    __syncthreads();
    mx = smx;

    float se = 0.f;
    for (int i = tid; i < Vc; i += 256) se += __expf(lr[i] - mx);
    #pragma unroll
    for (int o = 16; o; o >>= 1) se += __shfl_xor_sync(0xffffffffu, se, o);
    if ((tid & 31) == 0) red2[tid >> 5] = se;
    __syncthreads();
    if (tid == 0) {
        float tot = 0.f;
        #pragma unroll
        for (int w = 0; w < 8; w++) tot += red2[w];
        int tg = targets[row];
        g_rowloss[row] = logf(tot) + mx - lr[tg];
    }
}

__global__ void loss_reduce_kernel(float* __restrict__ out) {
    int tid = threadIdx.x;
    __shared__ float red[8];
    float s = 0.f;
    for (int i = tid; i < Mc; i += 256) s += g_rowloss[i];
    #pragma unroll
    for (int o = 16; o; o >>= 1) s += __shfl_xor_sync(0xffffffffu, s, o);
    if ((tid & 31) == 0) red[tid >> 5] = s;
    __syncthreads();
    if (tid == 0) {
        float tot = 0.f;
        #pragma unroll
        for (int w = 0; w < 8; w++) tot += red[w];
        out[0] = tot / (float)Mc;
    }
}

// ---------------- host driver ----------------
extern "C" void kernel_launch(void* const* d_in, const int* in_sizes, int n_in,
                              void* d_out, int out_size) {
    (void)in_sizes; (void)n_in;
    const int*   idx     = (const int*)  d_in[0];
    const int*   targets = (const int*)  d_in[1];
    const float* tok_emb = (const float*)d_in[2];
    const float* pos_emb = (const float*)d_in[3];
    const float* Wq      = (const float*)d_in[4];
    const float* Wk      = (const float*)d_in[5];
    const float* Wv      = (const float*)d_in[6];
    const float* Wproj   = (const float*)d_in[7];
    const float* bproj   = (const float*)d_in[8];
    const float* ln1_g   = (const float*)d_in[9];
    const float* ln1_b   = (const float*)d_in[10];
    const float* ln2_g   = (const float*)d_in[11];
    const float* ln2_b   = (const float*)d_in[12];
    const float* W1      = (const float*)d_in[13];
    const float* b1      = (const float*)d_in[14];
    const float* W2      = (const float*)d_in[15];
    const float* b2      = (const float*)d_in[16];
    const float* lnf_g   = (const float*)d_in[17];
    const float* lnf_b   = (const float*)d_in[18];
    const float* Whead   = (const float*)d_in[19];
    const float* bhead   = (const float*)d_in[20];

    float *xp, *hp, *wtp, *qkvp, *attp, *fp, *lgp;
    __nv_bfloat16 *ahp, *alp, *bhp, *blp;
    cudaGetSymbolAddress((void**)&xp,   g_x);
    cudaGetSymbolAddress((void**)&hp,   g_h);
    cudaGetSymbolAddress((void**)&wtp,  g_wt);
    cudaGetSymbolAddress((void**)&qkvp, g_qkv);
    cudaGetSymbolAddress((void**)&attp, g_att);
    cudaGetSymbolAddress((void**)&fp,   g_f);
    cudaGetSymbolAddress((void**)&lgp,  g_logits);
    cudaGetSymbolAddress((void**)&ahp,  g_ah);
    cudaGetSymbolAddress((void**)&alp,  g_al);
    cudaGetSymbolAddress((void**)&bhp,  g_bh);
    cudaGetSymbolAddress((void**)&blp,  g_bl);

    cudaFuncSetAttribute(hgemm2<false, false, false>,
                         cudaFuncAttributeMaxDynamicSharedMemorySize, HG2_SMEM);
    cudaFuncSetAttribute(hgemm2<true, false, true>,
                         cudaFuncAttributeMaxDynamicSharedMemorySize, HG2_SMEM);
    cudaFuncSetAttribute(hgemm2<true, true, false>,
                         cudaFuncAttributeMaxDynamicSharedMemorySize, HG2_SMEM);
    cudaFuncSetAttribute(hgemm2<true, false, false>,
                         cudaFuncAttributeMaxDynamicSharedMemorySize, HG2_SMEM);

    embed_kernel<<<Mc, 256>>>(idx, tok_emb, pos_emb);

    for (int l = 0; l < Lc; l++) {
        // ---- attention block ----
        ln_kernel<<<Mc, 256>>>(xp, hp, ln1_g + (size_t)l * Ec, ln1_b + (size_t)l * Ec);
        convA_kernel<<<(Mc * Ec) / 8 / 256, 256>>>(hp, ahp, alp, Ec);
        rearrange_kernel<<<(3 * Ec * Ec) / 256, 256>>>(Wq, Wk, Wv, l);
        convB_kernel<<<dim3(3 * Ec / 64, Ec / 32), 256>>>(wtp, bhp, blp, Ec, 3 * Ec);
        hgemm2<false, false, false><<<dim3(Mc / 256, 3 * Ec / 128), 256, HG2_SMEM>>>(
            ahp, alp, bhp, blp, (const float*)nullptr, qkvp, 3 * Ec, Ec);
        attn_kernel<<<dim3(Tc / 64, Hc, Bc), 256>>>();
        convA_kernel<<<(Mc * Ec) / 8 / 256, 256>>>(attp, ahp, alp, Ec);
        convB_kernel<<<dim3(Ec / 64, Ec / 32), 256>>>(
            Wproj + (size_t)l * Ec * Ec, bhp, blp, Ec, Ec);
        hgemm2<true, false, true><<<dim3(Mc / 256, Ec / 128), 256, HG2_SMEM>>>(
            ahp, alp, bhp, blp, bproj + (size_t)l * Ec, xp, Ec, Ec);
        // ---- MLP block ----
        ln_kernel<<<Mc, 256>>>(xp, hp, ln2_g + (size_t)l * Ec, ln2_b + (size_t)l * Ec);
        convA_kernel<<<(Mc * Ec) / 8 / 256, 256>>>(hp, ahp, alp, Ec);
        convB_kernel<<<dim3(FFc / 64, Ec / 32), 256>>>(
            W1 + (size_t)l * Ec * FFc, bhp, blp, Ec, FFc);
        hgemm2<true, true, false><<<dim3(Mc / 256, FFc / 128), 256, HG2_SMEM>>>(
            ahp, alp, bhp, blp, b1 + (size_t)l * FFc, fp, FFc, Ec);
        convA_kernel<<<((size_t)Mc * FFc) / 8 / 256, 256>>>(fp, ahp, alp, FFc);
        convB_kernel<<<dim3(Ec / 64, FFc / 32), 256>>>(
            W2 + (size_t)l * FFc * Ec, bhp, blp, FFc, Ec);
        hgemm2<true, false, true><<<dim3(Mc / 256, Ec / 128), 256, HG2_SMEM>>>(
            ahp, alp, bhp, blp, b2 + (size_t)l * Ec, xp, Ec, FFc);
    }

    ln_kernel<<<Mc, 256>>>(xp, hp, lnf_g, lnf_b);

    const size_t MV = (size_t)Mc * Vc;
    float* logits;
    float* lossptr = nullptr;
    if ((size_t)out_size >= MV) {
        logits = (float*)d_out;
        if ((size_t)out_size > MV) lossptr = (float*)d_out + MV;
    } else {
        logits = lgp;
        lossptr = (float*)d_out;
    }

    convA_kernel<<<(Mc * Ec) / 8 / 256, 256>>>(hp, ahp, alp, Ec);
    convB_kernel<<<dim3(Vc / 64, Ec / 32), 256>>>(Whead, bhp, blp, Ec, Vc);
    hgemm2<true, false, false><<<dim3(Mc / 256, Vc / 128), 256, HG2_SMEM>>>(
        ahp, alp, bhp, blp, bhead, logits, Vc, Ec);

    if (lossptr) {
        rowloss_kernel<<<Mc, 256>>>(logits, targets);
        loss_reduce_kernel<<<1, 256>>>(lossptr);
    }
}